// round 11
// baseline (speedup 1.0000x reference)
#include <cuda_runtime.h>
#include <cuda_bf16.h>
#include <cstdint>

// ---------------- problem constants ----------------
#define T_TOK 4096
#define DIMV  4096
#define HQ    32
#define KVH   8
#define HDIM  128
#define BATCH 2
#define SEQ   2048
#define WIN   1024

// ---------------- scratch (device globals) ----------------
__device__ float g_q [(size_t)T_TOK * HQ  * HDIM];
__device__ float g_k [(size_t)T_TOK * KVH * HDIM];
__device__ float g_v [(size_t)T_TOK * KVH * HDIM];
__device__ __nv_bfloat16 g_a_hi[(size_t)4096 * 4096];
__device__ __nv_bfloat16 g_a_lo[(size_t)4096 * 4096];
__device__ __nv_bfloat16 g_w_hi[(size_t)4096 * 4096];
__device__ __nv_bfloat16 g_w_lo[(size_t)4096 * 4096];

typedef unsigned long long ull;

// ---------------- helpers ----------------
__device__ __forceinline__ uint32_t smem_u32(const void* p) {
    uint32_t a;
    asm("{ .reg .u64 t; cvta.to.shared.u64 t, %1; cvt.u32.u64 %0, t; }" : "=r"(a) : "l"(p));
    return a;
}

#define LDSM4(r, addr) \
    asm volatile("ldmatrix.sync.aligned.m8n8.x4.shared.b16 {%0,%1,%2,%3}, [%4];" \
        : "=r"((r)[0]), "=r"((r)[1]), "=r"((r)[2]), "=r"((r)[3]) : "r"(addr))

#define LDSM4T(r, addr) \
    asm volatile("ldmatrix.sync.aligned.m8n8.x4.trans.shared.b16 {%0,%1,%2,%3}, [%4];" \
        : "=r"((r)[0]), "=r"((r)[1]), "=r"((r)[2]), "=r"((r)[3]) : "r"(addr))

#define MMA16816(d, a, b0_, b1_) \
    asm volatile("mma.sync.aligned.m16n8k16.row.col.f32.bf16.bf16.f32 " \
        "{%0,%1,%2,%3}, {%4,%5,%6,%7}, {%8,%9}, {%0,%1,%2,%3};" \
        : "+f"((d)[0]), "+f"((d)[1]), "+f"((d)[2]), "+f"((d)[3]) \
        : "r"((a)[0]), "r"((a)[1]), "r"((a)[2]), "r"((a)[3]), "r"(b0_), "r"(b1_))

#define CP16(s, g) \
    asm volatile("cp.async.cg.shared.global [%0], [%1], 16;" :: "r"(s), "l"(g) : "memory")
#define CP_COMMIT() asm volatile("cp.async.commit_group;" ::: "memory")
#define CP_WAIT1()  asm volatile("cp.async.wait_group 1;" ::: "memory")
#define CP_WAIT0()  asm volatile("cp.async.wait_group 0;" ::: "memory")

// split one fp32 into hi/lo bf16
__device__ __forceinline__ void split1(float v, __nv_bfloat16& h, __nv_bfloat16& l) {
    h = __float2bfloat16(v);
    l = __float2bfloat16(v - __bfloat162float(h));
}
__device__ __forceinline__ void split4_store(__nv_bfloat16* hp, __nv_bfloat16* lp, float4 v) {
    __nv_bfloat16 h0, h1, h2, h3, l0, l1, l2, l3;
    split1(v.x, h0, l0); split1(v.y, h1, l1);
    split1(v.z, h2, l2); split1(v.w, h3, l3);
    *(__nv_bfloat162*)(hp)     = __nv_bfloat162(h0, h1);
    *(__nv_bfloat162*)(hp + 2) = __nv_bfloat162(h2, h3);
    *(__nv_bfloat162*)(lp)     = __nv_bfloat162(l0, l1);
    *(__nv_bfloat162*)(lp + 2) = __nv_bfloat162(l2, l3);
}

// ================= conversion kernels =================
__global__ void cvt_split(const float* __restrict__ s,
                          __nv_bfloat16* __restrict__ h, __nv_bfloat16* __restrict__ l)
{
    size_t i = ((size_t)blockIdx.x * blockDim.x + threadIdx.x) * 4;
    float4 v = *(const float4*)(s + i);
    split4_store(h + i, l + i, v);
}

// W[K,N] fp32 -> Wt[N,K] (hi, lo) bf16. block (32,8), grid (N/32, K/32)
__global__ void cvt_wt(const float* __restrict__ w,
                       __nv_bfloat16* __restrict__ th, __nv_bfloat16* __restrict__ tl,
                       int K, int N)
{
    __shared__ float t[32][33];
    int n0 = blockIdx.x * 32, k0 = blockIdx.y * 32;
    int tx = threadIdx.x, ty = threadIdx.y;
#pragma unroll
    for (int j = 0; j < 4; j++)
        t[ty + 8 * j][tx] = w[(size_t)(k0 + ty + 8 * j) * N + n0 + tx];
    __syncthreads();
#pragma unroll
    for (int j = 0; j < 4; j++) {
        float v = t[tx][ty + 8 * j];
        __nv_bfloat16 h, l;
        split1(v, h, l);
        size_t o = (size_t)(n0 + ty + 8 * j) * K + k0 + tx;
        th[o] = h; tl[o] = l;
    }
}

// ================= HMMA GEMM with cp.async 3-stage pipeline =================
// C[M,N] = A[M,K] @ Wt[N,K]^T, split-bf16 3-term. Tile 128x128, BK=32, 256 thr.
#define ROWP 40
#define MAT_ELEM (128 * ROWP)
#define BUF_ELEM (4 * MAT_ELEM)
#define AL_OFF (MAT_ELEM)
#define BH_OFF (2 * MAT_ELEM)
#define BL_OFF (3 * MAT_ELEM)
#define GEMM_SMEM (3 * BUF_ELEM * 2)   // 122880 bytes, 3 stages

__global__ __launch_bounds__(256) void gemm_mma(
    const __nv_bfloat16* __restrict__ ah, const __nv_bfloat16* __restrict__ al,
    const __nv_bfloat16* __restrict__ bh, const __nv_bfloat16* __restrict__ bl,
    float* __restrict__ C, int K, int N)
{
    extern __shared__ __nv_bfloat16 sm[];
    const uint32_t s_base = smem_u32(sm);

    const int tid  = threadIdx.x;
    const int wid  = tid >> 5;
    const int lane = tid & 31;
    const int bm   = blockIdx.y * 128;
    const int bn   = blockIdx.x * 128;
    const int m_off = (wid & 3) * 32;
    const int n_off = (wid >> 2) * 64;

    const int lr = tid >> 2;
    const int lc = (tid & 3) * 8;

    const int a_row = m_off + (lane & 15);
    const int a_kof = (lane >> 4) * 8;
    const int b_n   = n_off + ((lane >> 4) << 3) + (lane & 7);
    const int b_k   = ((lane >> 3) & 1) * 8;

    float acc[2][8][4];
#pragma unroll
    for (int mi = 0; mi < 2; mi++)
#pragma unroll
        for (int nj = 0; nj < 8; nj++)
#pragma unroll
            for (int u = 0; u < 4; u++) acc[mi][nj][u] = 0.f;

    const int NIT = K >> 5;

    // async copy of one K-chunk into stage (it % 3)
    auto CPA = [&](int it) {
        uint32_t base = s_base + (uint32_t)((it % 3) * BUF_ELEM * 2);
        size_t k0 = (size_t)it << 5;
#pragma unroll
        for (int j = 0; j < 2; j++) {
            int r = lr + j * 64;
            uint32_t o = (uint32_t)((r * ROWP + lc) * 2);
            size_t oa = (size_t)(bm + r) * K + k0 + lc;
            size_t ob = (size_t)(bn + r) * K + k0 + lc;
            CP16(base + o,                ah + oa);
            CP16(base + AL_OFF * 2 + o,   al + oa);
            CP16(base + BH_OFF * 2 + o,   bh + ob);
            CP16(base + BL_OFF * 2 + o,   bl + ob);
        }
        CP_COMMIT();
    };

    CPA(0);
    if (NIT > 1) CPA(1);

    for (int it = 0; it < NIT; it++) {
        if (it + 1 < NIT) { CP_WAIT1(); } else { CP_WAIT0(); }
        __syncthreads();                 // stage it%3 ready; all warps done with (it-1)%3
        if (it + 2 < NIT) CPA(it + 2);   // prefetch into (it+2)%3 (== (it-1)%3, now free)

        const uint32_t sbuf = s_base + (uint32_t)((it % 3) * BUF_ELEM * 2);
#pragma unroll
        for (int ks = 0; ks < 2; ks++) {
            uint32_t ahf[2][4], alf[2][4];
            {
                uint32_t r0 = sbuf + (uint32_t)((a_row * ROWP + ks * 16 + a_kof) * 2);
                uint32_t r1 = r0 + 16 * ROWP * 2;
                LDSM4(ahf[0], r0);
                LDSM4(ahf[1], r1);
                LDSM4(alf[0], r0 + AL_OFF * 2);
                LDSM4(alf[1], r1 + AL_OFF * 2);
            }
#pragma unroll
            for (int p = 0; p < 4; p++) {
                uint32_t bb = sbuf + (uint32_t)(BH_OFF * 2) +
                              (uint32_t)(((b_n + p * 16) * ROWP + ks * 16 + b_k) * 2);
                uint32_t bhf[4], blf[4];
                LDSM4(bhf, bb);
                LDSM4(blf, bb + (BL_OFF - BH_OFF) * 2);
                const int nj0 = p * 2;
                MMA16816(acc[0][nj0],     ahf[0], bhf[0], bhf[1]);
                MMA16816(acc[0][nj0 + 1], ahf[0], bhf[2], bhf[3]);
                MMA16816(acc[1][nj0],     ahf[1], bhf[0], bhf[1]);
                MMA16816(acc[1][nj0 + 1], ahf[1], bhf[2], bhf[3]);
                MMA16816(acc[0][nj0],     ahf[0], blf[0], blf[1]);
                MMA16816(acc[0][nj0 + 1], ahf[0], blf[2], blf[3]);
                MMA16816(acc[1][nj0],     ahf[1], blf[0], blf[1]);
                MMA16816(acc[1][nj0 + 1], ahf[1], blf[2], blf[3]);
                MMA16816(acc[0][nj0],     alf[0], bhf[0], bhf[1]);
                MMA16816(acc[0][nj0 + 1], alf[0], bhf[2], bhf[3]);
                MMA16816(acc[1][nj0],     alf[1], bhf[0], bhf[1]);
                MMA16816(acc[1][nj0 + 1], alf[1], bhf[2], bhf[3]);
            }
        }
    }

    const int eg = lane >> 2, et = lane & 3;
#pragma unroll
    for (int mi = 0; mi < 2; mi++)
#pragma unroll
    for (int nj = 0; nj < 8; nj++) {
        float* c = C + (size_t)(bm + m_off + mi * 16 + eg) * N + bn + n_off + nj * 8 + et * 2;
        *(float2*)c                   = make_float2(acc[mi][nj][0], acc[mi][nj][1]);
        *(float2*)(c + (size_t)8 * N) = make_float2(acc[mi][nj][2], acc[mi][nj][3]);
    }
}

// ================= RoPE =================
__global__ void rope_kernel(float* __restrict__ t, const float* __restrict__ cs,
                            const float* __restrict__ sn, int heads)
{
    int idx = blockIdx.x * blockDim.x + threadIdx.x;
    int i   = idx & 63;
    int h   = (idx >> 6) % heads;
    int tok = idx / (64 * heads);
    float c = cs[tok * 64 + i];
    float s = sn[tok * 64 + i];
    float* p = t + ((size_t)tok * heads + h) * HDIM + 2 * i;
    float t0 = p[0], t1 = p[1];
    p[0] = t0 * c - t1 * s;
    p[1] = t0 * s + t1 * c;
}

// ================= HMMA windowed flash attention =================
// Epilogue writes split hi/lo bf16 directly into the wo-GEMM A buffers.
#define AQ_STR 136
#define AP_STR 72
#define S_QH 0
#define S_QL (128 * AQ_STR)
#define S_KH (2 * 128 * AQ_STR)
#define S_KL (S_KH + 64 * AQ_STR)
#define S_VH (S_KL + 64 * AQ_STR)
#define S_VL (S_VH + 64 * AQ_STR)
#define S_PH (S_VL + 64 * AQ_STR)
#define S_PL (S_PH + 128 * AP_STR)
#define ATTN_ELEM (S_PL + 128 * AP_STR)
#define ATTN_SMEM (ATTN_ELEM * 2)

__global__ __launch_bounds__(256) void attn_mma(
    const float* __restrict__ q, const float* __restrict__ k,
    const float* __restrict__ v,
    __nv_bfloat16* __restrict__ oh, __nv_bfloat16* __restrict__ ol)
{
    extern __shared__ __nv_bfloat16 smb[];
    const uint32_t s_base = smem_u32(smb);

    const int tid  = threadIdx.x;
    const int wid  = tid >> 5;
    const int lane = tid & 31;
    const int h    = blockIdx.y;
    const int b    = blockIdx.z;
    const int kvh  = h >> 2;
    const int i0   = blockIdx.x * 128;
    const int qb2  = blockIdx.x * 2;
    const int tok0 = b * SEQ + i0;

    const float scale = 0.08838834764831845f;

    for (int i = tid; i < 128 * 32; i += 256) {
        int r = i >> 5, c = (i & 31) * 4;
        float4 vq = *(const float4*)(q + ((size_t)(tok0 + r) * HQ + h) * HDIM + c);
        vq.x *= scale; vq.y *= scale; vq.z *= scale; vq.w *= scale;
        split4_store(smb + S_QH + r * AQ_STR + c, smb + S_QL + r * AQ_STR + c, vq);
    }

    const int iw    = i0 + wid * 16;
    const int rl    = lane >> 2;
    const int cq    = (lane & 3) * 2;
    const int a_row = wid * 16 + (lane & 15);
    const int a_kof = (lane >> 4) * 8;
    const int kb_r  = ((lane >> 4) << 3) + (lane & 7);
    const int kb_k  = ((lane >> 3) & 1) * 8;
    const int v_row = lane & 15;
    const int v_col = (lane >> 4) * 8;

    float m_lo = -1e30f, m_hi = -1e30f, l_lo = 0.f, l_hi = 0.f;
    float o_acc[16][4];
#pragma unroll
    for (int nj = 0; nj < 16; nj++)
#pragma unroll
        for (int u = 0; u < 4; u++) o_acc[nj][u] = 0.f;

    int jb_lo = qb2 - 16; if (jb_lo < 0) jb_lo = 0;
    const int jb_hi = qb2 + 1;

    for (int jb = jb_lo; jb <= jb_hi; jb++) {
        const int j0 = jb * 64;
        __syncthreads();

        for (int i = tid; i < 64 * 32; i += 256) {
            int r = i >> 5, c = (i & 31) * 4;
            size_t off = ((size_t)(b * SEQ + j0 + r) * KVH + kvh) * HDIM + c;
            float4 kk = *(const float4*)(k + off);
            float4 vv = *(const float4*)(v + off);
            split4_store(smb + S_KH + r * AQ_STR + c, smb + S_KL + r * AQ_STR + c, kk);
            split4_store(smb + S_VH + r * AQ_STR + c, smb + S_VL + r * AQ_STR + c, vv);
        }
        __syncthreads();

        if (j0 > iw + 15 || j0 + 63 < iw - (WIN - 1)) continue;

        float s_acc[8][4];
#pragma unroll
        for (int nj = 0; nj < 8; nj++)
#pragma unroll
            for (int u = 0; u < 4; u++) s_acc[nj][u] = 0.f;

#pragma unroll
        for (int ks = 0; ks < 8; ks++) {
            uint32_t qh_f[4], ql_f[4];
            uint32_t aq = s_base + (uint32_t)((a_row * AQ_STR + ks * 16 + a_kof) * 2);
            LDSM4(qh_f, aq + S_QH * 2);
            LDSM4(ql_f, aq + S_QL * 2);
#pragma unroll
            for (int kp2 = 0; kp2 < 4; kp2 += 2) {
                uint32_t kh0[4], kl0[4], kh1[4], kl1[4];
                uint32_t ab0 = s_base + (uint32_t)((((kp2)     * 16 + kb_r) * AQ_STR + ks * 16 + kb_k) * 2);
                uint32_t ab1 = s_base + (uint32_t)((((kp2 + 1) * 16 + kb_r) * AQ_STR + ks * 16 + kb_k) * 2);
                LDSM4(kh0, ab0 + S_KH * 2);
                LDSM4(kl0, ab0 + S_KL * 2);
                LDSM4(kh1, ab1 + S_KH * 2);
                LDSM4(kl1, ab1 + S_KL * 2);
                const int a0 = kp2 * 2;
                MMA16816(s_acc[a0 + 0], qh_f, kh0[0], kh0[1]);
                MMA16816(s_acc[a0 + 1], qh_f, kh0[2], kh0[3]);
                MMA16816(s_acc[a0 + 2], qh_f, kh1[0], kh1[1]);
                MMA16816(s_acc[a0 + 3], qh_f, kh1[2], kh1[3]);
                MMA16816(s_acc[a0 + 0], qh_f, kl0[0], kl0[1]);
                MMA16816(s_acc[a0 + 1], qh_f, kl0[2], kl0[3]);
                MMA16816(s_acc[a0 + 2], qh_f, kl1[0], kl1[1]);
                MMA16816(s_acc[a0 + 3], qh_f, kl1[2], kl1[3]);
                MMA16816(s_acc[a0 + 0], ql_f, kh0[0], kh0[1]);
                MMA16816(s_acc[a0 + 1], ql_f, kh0[2], kh0[3]);
                MMA16816(s_acc[a0 + 2], ql_f, kh1[0], kh1[1]);
                MMA16816(s_acc[a0 + 3], ql_f, kh1[2], kh1[3]);
            }
        }

        const int i_lo = iw + rl;
        const int i_hi = i_lo + 8;
#pragma unroll
        for (int nj = 0; nj < 8; nj++) {
            int jg = j0 + nj * 8 + cq;
            if (jg     > i_lo || i_lo - jg     >= WIN) s_acc[nj][0] = -1e30f;
            if (jg + 1 > i_lo || i_lo - jg - 1 >= WIN) s_acc[nj][1] = -1e30f;
            if (jg     > i_hi || i_hi - jg     >= WIN) s_acc[nj][2] = -1e30f;
            if (jg + 1 > i_hi || i_hi - jg - 1 >= WIN) s_acc[nj][3] = -1e30f;
        }
        float mx_lo = -1e30f, mx_hi = -1e30f;
#pragma unroll
        for (int nj = 0; nj < 8; nj++) {
            mx_lo = fmaxf(mx_lo, fmaxf(s_acc[nj][0], s_acc[nj][1]));
            mx_hi = fmaxf(mx_hi, fmaxf(s_acc[nj][2], s_acc[nj][3]));
        }
        mx_lo = fmaxf(mx_lo, __shfl_xor_sync(0xffffffffu, mx_lo, 1));
        mx_lo = fmaxf(mx_lo, __shfl_xor_sync(0xffffffffu, mx_lo, 2));
        mx_hi = fmaxf(mx_hi, __shfl_xor_sync(0xffffffffu, mx_hi, 1));
        mx_hi = fmaxf(mx_hi, __shfl_xor_sync(0xffffffffu, mx_hi, 2));

        float mn_lo = fmaxf(m_lo, mx_lo);
        float mn_hi = fmaxf(m_hi, mx_hi);
        float f_lo = __expf(m_lo - mn_lo);
        float f_hi = __expf(m_hi - mn_hi);
        m_lo = mn_lo; m_hi = mn_hi;

        float sum_lo = 0.f, sum_hi = 0.f;
#pragma unroll
        for (int nj = 0; nj < 8; nj++) {
            float p0 = __expf(s_acc[nj][0] - mn_lo);
            float p1 = __expf(s_acc[nj][1] - mn_lo);
            float p2 = __expf(s_acc[nj][2] - mn_hi);
            float p3 = __expf(s_acc[nj][3] - mn_hi);
            sum_lo += p0 + p1;
            sum_hi += p2 + p3;
            __nv_bfloat16 h0, h1, h2, h3, l0, l1, l2, l3;
            split1(p0, h0, l0); split1(p1, h1, l1);
            split1(p2, h2, l2); split1(p3, h3, l3);
            int co = nj * 8 + cq;
            *(__nv_bfloat162*)(smb + S_PH + (wid * 16 + rl) * AP_STR + co)     = __nv_bfloat162(h0, h1);
            *(__nv_bfloat162*)(smb + S_PL + (wid * 16 + rl) * AP_STR + co)     = __nv_bfloat162(l0, l1);
            *(__nv_bfloat162*)(smb + S_PH + (wid * 16 + rl + 8) * AP_STR + co) = __nv_bfloat162(h2, h3);
            *(__nv_bfloat162*)(smb + S_PL + (wid * 16 + rl + 8) * AP_STR + co) = __nv_bfloat162(l2, l3);
        }
        sum_lo += __shfl_xor_sync(0xffffffffu, sum_lo, 1);
        sum_lo += __shfl_xor_sync(0xffffffffu, sum_lo, 2);
        sum_hi += __shfl_xor_sync(0xffffffffu, sum_hi, 1);
        sum_hi += __shfl_xor_sync(0xffffffffu, sum_hi, 2);
        l_lo = l_lo * f_lo + sum_lo;
        l_hi = l_hi * f_hi + sum_hi;

#pragma unroll
        for (int nj = 0; nj < 16; nj++) {
            o_acc[nj][0] *= f_lo; o_acc[nj][1] *= f_lo;
            o_acc[nj][2] *= f_hi; o_acc[nj][3] *= f_hi;
        }
        __syncwarp();

#pragma unroll
        for (int kc = 0; kc < 4; kc++) {
            uint32_t ph_f[4], pl_f[4];
            uint32_t ap = s_base + (uint32_t)((a_row * AP_STR + kc * 16 + a_kof) * 2);
            LDSM4(ph_f, ap + S_PH * 2);
            LDSM4(pl_f, ap + S_PL * 2);
#pragma unroll
            for (int nb2 = 0; nb2 < 8; nb2 += 2) {
                uint32_t vh0[4], vl0[4], vh1[4], vl1[4];
                uint32_t av0 = s_base + (uint32_t)(((kc * 16 + v_row) * AQ_STR + (nb2)     * 16 + v_col) * 2);
                uint32_t av1 = s_base + (uint32_t)(((kc * 16 + v_row) * AQ_STR + (nb2 + 1) * 16 + v_col) * 2);
                LDSM4T(vh0, av0 + S_VH * 2);
                LDSM4T(vl0, av0 + S_VL * 2);
                LDSM4T(vh1, av1 + S_VH * 2);
                LDSM4T(vl1, av1 + S_VL * 2);
                const int a0 = nb2 * 2;
                MMA16816(o_acc[a0 + 0], ph_f, vh0[0], vh0[1]);
                MMA16816(o_acc[a0 + 1], ph_f, vh0[2], vh0[3]);
                MMA16816(o_acc[a0 + 2], ph_f, vh1[0], vh1[1]);
                MMA16816(o_acc[a0 + 3], ph_f, vh1[2], vh1[3]);
                MMA16816(o_acc[a0 + 0], ph_f, vl0[0], vl0[1]);
                MMA16816(o_acc[a0 + 1], ph_f, vl0[2], vl0[3]);
                MMA16816(o_acc[a0 + 2], ph_f, vl1[0], vl1[1]);
                MMA16816(o_acc[a0 + 3], ph_f, vl1[2], vl1[3]);
                MMA16816(o_acc[a0 + 0], pl_f, vh0[0], vh0[1]);
                MMA16816(o_acc[a0 + 1], pl_f, vh0[2], vh0[3]);
                MMA16816(o_acc[a0 + 2], pl_f, vh1[0], vh1[1]);
                MMA16816(o_acc[a0 + 3], pl_f, vh1[2], vh1[3]);
            }
        }
    }

    // ---- epilogue: O / l -> split hi/lo bf16 directly (feeds wo GEMM) ----
    float inv_lo = 1.0f / l_lo;
    float inv_hi = 1.0f / l_hi;
    const int i_lo = iw + rl;
#pragma unroll
    for (int nj = 0; nj < 16; nj++) {
        int col = nj * 8 + cq;
        size_t o0 = ((size_t)(b * SEQ + i_lo)     * HQ + h) * HDIM + col;
        size_t o1 = ((size_t)(b * SEQ + i_lo + 8) * HQ + h) * HDIM + col;
        float v0 = o_acc[nj][0] * inv_lo, v1 = o_acc[nj][1] * inv_lo;
        float v2 = o_acc[nj][2] * inv_hi, v3 = o_acc[nj][3] * inv_hi;
        __nv_bfloat16 h0, h1, h2, h3, l0, l1, l2, l3;
        split1(v0, h0, l0); split1(v1, h1, l1);
        split1(v2, h2, l2); split1(v3, h3, l3);
        *(__nv_bfloat162*)(oh + o0) = __nv_bfloat162(h0, h1);
        *(__nv_bfloat162*)(ol + o0) = __nv_bfloat162(l0, l1);
        *(__nv_bfloat162*)(oh + o1) = __nv_bfloat162(h2, h3);
        *(__nv_bfloat162*)(ol + o1) = __nv_bfloat162(l2, l3);
    }
}

// ================= launch =================
extern "C" void kernel_launch(void* const* d_in, const int* in_sizes, int n_in,
                              void* d_out, int out_size)
{
    (void)in_sizes; (void)n_in; (void)out_size;
    const float* x  = (const float*)d_in[0];
    const float* cs = (const float*)d_in[1];
    const float* sn = (const float*)d_in[2];
    const float* wq = (const float*)d_in[3];
    const float* wk = (const float*)d_in[4];
    const float* wv = (const float*)d_in[5];
    const float* wo = (const float*)d_in[6];
    float* out = (float*)d_out;

    float *qp, *kp, *vp;
    __nv_bfloat16 *ahp, *alp, *whp, *wlp;
    cudaGetSymbolAddress((void**)&qp,  g_q);
    cudaGetSymbolAddress((void**)&kp,  g_k);
    cudaGetSymbolAddress((void**)&vp,  g_v);
    cudaGetSymbolAddress((void**)&ahp, g_a_hi);
    cudaGetSymbolAddress((void**)&alp, g_a_lo);
    cudaGetSymbolAddress((void**)&whp, g_w_hi);
    cudaGetSymbolAddress((void**)&wlp, g_w_lo);

    cudaFuncSetAttribute(gemm_mma, cudaFuncAttributeMaxDynamicSharedMemorySize, GEMM_SMEM);
    cudaFuncSetAttribute(attn_mma, cudaFuncAttributeMaxDynamicSharedMemorySize, ATTN_SMEM);

    const int NELEM = T_TOK * DIMV;
    dim3 cvtb(32, 8);

    // x -> hi/lo
    cvt_split<<<(NELEM / 4) / 256, 256>>>(x, ahp, alp);

    // Q = x @ wq
    cvt_wt<<<dim3((HQ * HDIM) / 32, DIMV / 32), cvtb>>>(wq, whp, wlp, DIMV, HQ * HDIM);
    gemm_mma<<<dim3((HQ * HDIM) / 128, T_TOK / 128), 256, GEMM_SMEM>>>(
        ahp, alp, whp, wlp, qp, DIMV, HQ * HDIM);

    // K = x @ wk
    cvt_wt<<<dim3((KVH * HDIM) / 32, DIMV / 32), cvtb>>>(wk, whp, wlp, DIMV, KVH * HDIM);
    gemm_mma<<<dim3((KVH * HDIM) / 128, T_TOK / 128), 256, GEMM_SMEM>>>(
        ahp, alp, whp, wlp, kp, DIMV, KVH * HDIM);

    // V = x @ wv
    cvt_wt<<<dim3((KVH * HDIM) / 32, DIMV / 32), cvtb>>>(wv, whp, wlp, DIMV, KVH * HDIM);
    gemm_mma<<<dim3((KVH * HDIM) / 128, T_TOK / 128), 256, GEMM_SMEM>>>(
        ahp, alp, whp, wlp, vp, DIMV, KVH * HDIM);

    // RoPE
    rope_kernel<<<(T_TOK * HQ  * 64) / 256, 256>>>(qp, cs, sn, HQ);
    rope_kernel<<<(T_TOK * KVH * 64) / 256, 256>>>(kp, cs, sn, KVH);

    // attention (HMMA) -> writes split hi/lo directly
    attn_mma<<<dim3(SEQ / 128, HQ, BATCH), 256, ATTN_SMEM>>>(qp, kp, vp, ahp, alp);

    // out = ao @ wo
    cvt_wt<<<dim3(DIMV / 32, (HQ * HDIM) / 32), cvtb>>>(wo, whp, wlp, HQ * HDIM, DIMV);
    gemm_mma<<<dim3(DIMV / 128, T_TOK / 128), 256, GEMM_SMEM>>>(
        ahp, alp, whp, wlp, out, HQ * HDIM, DIMV);
}

// round 12
// speedup vs baseline: 1.1859x; 1.1859x over previous
#include <cuda_runtime.h>
#include <cuda_bf16.h>
#include <cstdint>

// ---------------- problem constants ----------------
#define T_TOK 4096
#define DIMV  4096
#define HQ    32
#define KVH   8
#define HDIM  128
#define BATCH 2
#define SEQ   2048
#define WIN   1024

// ---------------- scratch (device globals) ----------------
__device__ float g_q [(size_t)T_TOK * HQ  * HDIM];
__device__ float g_k [(size_t)T_TOK * KVH * HDIM];
__device__ float g_v [(size_t)T_TOK * KVH * HDIM];
__device__ __nv_bfloat16 g_a_hi[(size_t)4096 * 4096];
__device__ __nv_bfloat16 g_a_lo[(size_t)4096 * 4096];
__device__ __nv_bfloat16 g_w_hi[(size_t)4096 * 4096];
__device__ __nv_bfloat16 g_w_lo[(size_t)4096 * 4096];

typedef unsigned long long ull;

// ---------------- helpers ----------------
__device__ __forceinline__ uint32_t smem_u32(const void* p) {
    uint32_t a;
    asm("{ .reg .u64 t; cvta.to.shared.u64 t, %1; cvt.u32.u64 %0, t; }" : "=r"(a) : "l"(p));
    return a;
}

#define LDSM4(r, addr) \
    asm volatile("ldmatrix.sync.aligned.m8n8.x4.shared.b16 {%0,%1,%2,%3}, [%4];" \
        : "=r"((r)[0]), "=r"((r)[1]), "=r"((r)[2]), "=r"((r)[3]) : "r"(addr))

#define LDSM4T(r, addr) \
    asm volatile("ldmatrix.sync.aligned.m8n8.x4.trans.shared.b16 {%0,%1,%2,%3}, [%4];" \
        : "=r"((r)[0]), "=r"((r)[1]), "=r"((r)[2]), "=r"((r)[3]) : "r"(addr))

#define MMA16816(d, a, b0_, b1_) \
    asm volatile("mma.sync.aligned.m16n8k16.row.col.f32.bf16.bf16.f32 " \
        "{%0,%1,%2,%3}, {%4,%5,%6,%7}, {%8,%9}, {%0,%1,%2,%3};" \
        : "+f"((d)[0]), "+f"((d)[1]), "+f"((d)[2]), "+f"((d)[3]) \
        : "r"((a)[0]), "r"((a)[1]), "r"((a)[2]), "r"((a)[3]), "r"(b0_), "r"(b1_))

#define CP16(s, g) \
    asm volatile("cp.async.cg.shared.global [%0], [%1], 16;" :: "r"(s), "l"(g) : "memory")
#define CP_COMMIT() asm volatile("cp.async.commit_group;" ::: "memory")
#define CP_WAIT0()  asm volatile("cp.async.wait_group 0;" ::: "memory")

// split one fp32 into hi/lo bf16
__device__ __forceinline__ void split1(float v, __nv_bfloat16& h, __nv_bfloat16& l) {
    h = __float2bfloat16(v);
    l = __float2bfloat16(v - __bfloat162float(h));
}
__device__ __forceinline__ void split4_store(__nv_bfloat16* hp, __nv_bfloat16* lp, float4 v) {
    __nv_bfloat16 h0, h1, h2, h3, l0, l1, l2, l3;
    split1(v.x, h0, l0); split1(v.y, h1, l1);
    split1(v.z, h2, l2); split1(v.w, h3, l3);
    *(__nv_bfloat162*)(hp)     = __nv_bfloat162(h0, h1);
    *(__nv_bfloat162*)(hp + 2) = __nv_bfloat162(h2, h3);
    *(__nv_bfloat162*)(lp)     = __nv_bfloat162(l0, l1);
    *(__nv_bfloat162*)(lp + 2) = __nv_bfloat162(l2, l3);
}

// ================= conversion kernels =================
__global__ void cvt_split(const float* __restrict__ s,
                          __nv_bfloat16* __restrict__ h, __nv_bfloat16* __restrict__ l)
{
    size_t i = ((size_t)blockIdx.x * blockDim.x + threadIdx.x) * 4;
    float4 v = *(const float4*)(s + i);
    split4_store(h + i, l + i, v);
}

// W[K,N] fp32 -> Wt[N,K] (hi, lo) bf16. block (32,8), grid (N/32, K/32)
__global__ void cvt_wt(const float* __restrict__ w,
                       __nv_bfloat16* __restrict__ th, __nv_bfloat16* __restrict__ tl,
                       int K, int N)
{
    __shared__ float t[32][33];
    int n0 = blockIdx.x * 32, k0 = blockIdx.y * 32;
    int tx = threadIdx.x, ty = threadIdx.y;
#pragma unroll
    for (int j = 0; j < 4; j++)
        t[ty + 8 * j][tx] = w[(size_t)(k0 + ty + 8 * j) * N + n0 + tx];
    __syncthreads();
#pragma unroll
    for (int j = 0; j < 4; j++) {
        float v = t[tx][ty + 8 * j];
        __nv_bfloat16 h, l;
        split1(v, h, l);
        size_t o = (size_t)(n0 + ty + 8 * j) * K + k0 + tx;
        th[o] = h; tl[o] = l;
    }
}

// ================= HMMA GEMM: cp.async 2-stage, 2 CTAs/SM =================
// C[M,N] = A[M,K] @ Wt[N,K]^T, split-bf16 3-term. Tile 128x128, BK=32, 256 thr.
#define ROWP 40
#define MAT_ELEM (128 * ROWP)
#define BUF_ELEM (4 * MAT_ELEM)
#define AL_OFF (MAT_ELEM)
#define BH_OFF (2 * MAT_ELEM)
#define BL_OFF (3 * MAT_ELEM)
#define GEMM_SMEM (2 * BUF_ELEM * 2)   // 81920 bytes -> 2 CTAs/SM

__global__ __launch_bounds__(256, 2) void gemm_mma(
    const __nv_bfloat16* __restrict__ ah, const __nv_bfloat16* __restrict__ al,
    const __nv_bfloat16* __restrict__ bh, const __nv_bfloat16* __restrict__ bl,
    float* __restrict__ C, int K, int N)
{
    extern __shared__ __nv_bfloat16 sm[];
    const uint32_t s_base = smem_u32(sm);

    const int tid  = threadIdx.x;
    const int wid  = tid >> 5;
    const int lane = tid & 31;
    const int bm   = blockIdx.y * 128;
    const int bn   = blockIdx.x * 128;
    const int m_off = (wid & 3) * 32;
    const int n_off = (wid >> 2) * 64;

    const int lr = tid >> 2;
    const int lc = (tid & 3) * 8;

    const int a_row = m_off + (lane & 15);
    const int a_kof = (lane >> 4) * 8;
    const int b_n   = n_off + ((lane >> 4) << 3) + (lane & 7);
    const int b_k   = ((lane >> 3) & 1) * 8;

    float acc[2][8][4];
#pragma unroll
    for (int mi = 0; mi < 2; mi++)
#pragma unroll
        for (int nj = 0; nj < 8; nj++)
#pragma unroll
            for (int u = 0; u < 4; u++) acc[mi][nj][u] = 0.f;

    const int NIT = K >> 5;

    // async copy of one K-chunk into stage (it & 1)
    auto CPA = [&](int it) {
        uint32_t base = s_base + (uint32_t)((it & 1) * BUF_ELEM * 2);
        size_t k0 = (size_t)it << 5;
#pragma unroll
        for (int j = 0; j < 2; j++) {
            int r = lr + j * 64;
            uint32_t o = (uint32_t)((r * ROWP + lc) * 2);
            size_t oa = (size_t)(bm + r) * K + k0 + lc;
            size_t ob = (size_t)(bn + r) * K + k0 + lc;
            CP16(base + o,              ah + oa);
            CP16(base + AL_OFF * 2 + o, al + oa);
            CP16(base + BH_OFF * 2 + o, bh + ob);
            CP16(base + BL_OFF * 2 + o, bl + ob);
        }
        CP_COMMIT();
    };

    CPA(0);

    for (int it = 0; it < NIT; it++) {
        CP_WAIT0();
        __syncthreads();                 // stage it&1 ready; prior compute on (it+1)&1 done
        if (it + 1 < NIT) CPA(it + 1);   // prefetch under this iter's compute

        const uint32_t sbuf = s_base + (uint32_t)((it & 1) * BUF_ELEM * 2);
#pragma unroll
        for (int ks = 0; ks < 2; ks++) {
            uint32_t ahf[2][4], alf[2][4];
            {
                uint32_t r0 = sbuf + (uint32_t)((a_row * ROWP + ks * 16 + a_kof) * 2);
                uint32_t r1 = r0 + 16 * ROWP * 2;
                LDSM4(ahf[0], r0);
                LDSM4(ahf[1], r1);
                LDSM4(alf[0], r0 + AL_OFF * 2);
                LDSM4(alf[1], r1 + AL_OFF * 2);
            }
#pragma unroll
            for (int p = 0; p < 4; p++) {
                uint32_t bb = sbuf + (uint32_t)(BH_OFF * 2) +
                              (uint32_t)(((b_n + p * 16) * ROWP + ks * 16 + b_k) * 2);
                uint32_t bhf[4], blf[4];
                LDSM4(bhf, bb);
                LDSM4(blf, bb + (BL_OFF - BH_OFF) * 2);
                const int nj0 = p * 2;
                MMA16816(acc[0][nj0],     ahf[0], bhf[0], bhf[1]);
                MMA16816(acc[0][nj0 + 1], ahf[0], bhf[2], bhf[3]);
                MMA16816(acc[1][nj0],     ahf[1], bhf[0], bhf[1]);
                MMA16816(acc[1][nj0 + 1], ahf[1], bhf[2], bhf[3]);
                MMA16816(acc[0][nj0],     ahf[0], blf[0], blf[1]);
                MMA16816(acc[0][nj0 + 1], ahf[0], blf[2], blf[3]);
                MMA16816(acc[1][nj0],     ahf[1], blf[0], blf[1]);
                MMA16816(acc[1][nj0 + 1], ahf[1], blf[2], blf[3]);
                MMA16816(acc[0][nj0],     alf[0], bhf[0], bhf[1]);
                MMA16816(acc[0][nj0 + 1], alf[0], bhf[2], bhf[3]);
                MMA16816(acc[1][nj0],     alf[1], bhf[0], bhf[1]);
                MMA16816(acc[1][nj0 + 1], alf[1], bhf[2], bhf[3]);
            }
        }
        __syncthreads();   // all warps done with stage it&1 before it is overwritten
    }

    const int eg = lane >> 2, et = lane & 3;
#pragma unroll
    for (int mi = 0; mi < 2; mi++)
#pragma unroll
    for (int nj = 0; nj < 8; nj++) {
        float* c = C + (size_t)(bm + m_off + mi * 16 + eg) * N + bn + n_off + nj * 8 + et * 2;
        *(float2*)c                   = make_float2(acc[mi][nj][0], acc[mi][nj][1]);
        *(float2*)(c + (size_t)8 * N) = make_float2(acc[mi][nj][2], acc[mi][nj][3]);
    }
}

// ================= RoPE =================
__global__ void rope_kernel(float* __restrict__ t, const float* __restrict__ cs,
                            const float* __restrict__ sn, int heads)
{
    int idx = blockIdx.x * blockDim.x + threadIdx.x;
    int i   = idx & 63;
    int h   = (idx >> 6) % heads;
    int tok = idx / (64 * heads);
    float c = cs[tok * 64 + i];
    float s = sn[tok * 64 + i];
    float* p = t + ((size_t)tok * heads + h) * HDIM + 2 * i;
    float t0 = p[0], t1 = p[1];
    p[0] = t0 * c - t1 * s;
    p[1] = t0 * s + t1 * c;
}

// ================= HMMA windowed flash attention =================
#define AQ_STR 136
#define AP_STR 72
#define S_QH 0
#define S_QL (128 * AQ_STR)
#define S_KH (2 * 128 * AQ_STR)
#define S_KL (S_KH + 64 * AQ_STR)
#define S_VH (S_KL + 64 * AQ_STR)
#define S_VL (S_VH + 64 * AQ_STR)
#define S_PH (S_VL + 64 * AQ_STR)
#define S_PL (S_PH + 128 * AP_STR)
#define ATTN_ELEM (S_PL + 128 * AP_STR)
#define ATTN_SMEM (ATTN_ELEM * 2)

__global__ __launch_bounds__(256) void attn_mma(
    const float* __restrict__ q, const float* __restrict__ k,
    const float* __restrict__ v,
    __nv_bfloat16* __restrict__ oh, __nv_bfloat16* __restrict__ ol)
{
    extern __shared__ __nv_bfloat16 smb[];
    const uint32_t s_base = smem_u32(smb);

    const int tid  = threadIdx.x;
    const int wid  = tid >> 5;
    const int lane = tid & 31;
    const int h    = blockIdx.y;
    const int b    = blockIdx.z;
    const int kvh  = h >> 2;
    const int i0   = blockIdx.x * 128;
    const int qb2  = blockIdx.x * 2;
    const int tok0 = b * SEQ + i0;

    const float scale = 0.08838834764831845f;

    for (int i = tid; i < 128 * 32; i += 256) {
        int r = i >> 5, c = (i & 31) * 4;
        float4 vq = *(const float4*)(q + ((size_t)(tok0 + r) * HQ + h) * HDIM + c);
        vq.x *= scale; vq.y *= scale; vq.z *= scale; vq.w *= scale;
        split4_store(smb + S_QH + r * AQ_STR + c, smb + S_QL + r * AQ_STR + c, vq);
    }

    const int iw    = i0 + wid * 16;
    const int rl    = lane >> 2;
    const int cq    = (lane & 3) * 2;
    const int a_row = wid * 16 + (lane & 15);
    const int a_kof = (lane >> 4) * 8;
    const int kb_r  = ((lane >> 4) << 3) + (lane & 7);
    const int kb_k  = ((lane >> 3) & 1) * 8;
    const int v_row = lane & 15;
    const int v_col = (lane >> 4) * 8;

    float m_lo = -1e30f, m_hi = -1e30f, l_lo = 0.f, l_hi = 0.f;
    float o_acc[16][4];
#pragma unroll
    for (int nj = 0; nj < 16; nj++)
#pragma unroll
        for (int u = 0; u < 4; u++) o_acc[nj][u] = 0.f;

    int jb_lo = qb2 - 16; if (jb_lo < 0) jb_lo = 0;
    const int jb_hi = qb2 + 1;

    for (int jb = jb_lo; jb <= jb_hi; jb++) {
        const int j0 = jb * 64;
        __syncthreads();

        for (int i = tid; i < 64 * 32; i += 256) {
            int r = i >> 5, c = (i & 31) * 4;
            size_t off = ((size_t)(b * SEQ + j0 + r) * KVH + kvh) * HDIM + c;
            float4 kk = *(const float4*)(k + off);
            float4 vv = *(const float4*)(v + off);
            split4_store(smb + S_KH + r * AQ_STR + c, smb + S_KL + r * AQ_STR + c, kk);
            split4_store(smb + S_VH + r * AQ_STR + c, smb + S_VL + r * AQ_STR + c, vv);
        }
        __syncthreads();

        if (j0 > iw + 15 || j0 + 63 < iw - (WIN - 1)) continue;

        float s_acc[8][4];
#pragma unroll
        for (int nj = 0; nj < 8; nj++)
#pragma unroll
            for (int u = 0; u < 4; u++) s_acc[nj][u] = 0.f;

#pragma unroll
        for (int ks = 0; ks < 8; ks++) {
            uint32_t qh_f[4], ql_f[4];
            uint32_t aq = s_base + (uint32_t)((a_row * AQ_STR + ks * 16 + a_kof) * 2);
            LDSM4(qh_f, aq + S_QH * 2);
            LDSM4(ql_f, aq + S_QL * 2);
#pragma unroll
            for (int kp2 = 0; kp2 < 4; kp2 += 2) {
                uint32_t kh0[4], kl0[4], kh1[4], kl1[4];
                uint32_t ab0 = s_base + (uint32_t)((((kp2)     * 16 + kb_r) * AQ_STR + ks * 16 + kb_k) * 2);
                uint32_t ab1 = s_base + (uint32_t)((((kp2 + 1) * 16 + kb_r) * AQ_STR + ks * 16 + kb_k) * 2);
                LDSM4(kh0, ab0 + S_KH * 2);
                LDSM4(kl0, ab0 + S_KL * 2);
                LDSM4(kh1, ab1 + S_KH * 2);
                LDSM4(kl1, ab1 + S_KL * 2);
                const int a0 = kp2 * 2;
                MMA16816(s_acc[a0 + 0], qh_f, kh0[0], kh0[1]);
                MMA16816(s_acc[a0 + 1], qh_f, kh0[2], kh0[3]);
                MMA16816(s_acc[a0 + 2], qh_f, kh1[0], kh1[1]);
                MMA16816(s_acc[a0 + 3], qh_f, kh1[2], kh1[3]);
                MMA16816(s_acc[a0 + 0], qh_f, kl0[0], kl0[1]);
                MMA16816(s_acc[a0 + 1], qh_f, kl0[2], kl0[3]);
                MMA16816(s_acc[a0 + 2], qh_f, kl1[0], kl1[1]);
                MMA16816(s_acc[a0 + 3], qh_f, kl1[2], kl1[3]);
                MMA16816(s_acc[a0 + 0], ql_f, kh0[0], kh0[1]);
                MMA16816(s_acc[a0 + 1], ql_f, kh0[2], kh0[3]);
                MMA16816(s_acc[a0 + 2], ql_f, kh1[0], kh1[1]);
                MMA16816(s_acc[a0 + 3], ql_f, kh1[2], kh1[3]);
            }
        }

        const int i_lo = iw + rl;
        const int i_hi = i_lo + 8;
#pragma unroll
        for (int nj = 0; nj < 8; nj++) {
            int jg = j0 + nj * 8 + cq;
            if (jg     > i_lo || i_lo - jg     >= WIN) s_acc[nj][0] = -1e30f;
            if (jg + 1 > i_lo || i_lo - jg - 1 >= WIN) s_acc[nj][1] = -1e30f;
            if (jg     > i_hi || i_hi - jg     >= WIN) s_acc[nj][2] = -1e30f;
            if (jg + 1 > i_hi || i_hi - jg - 1 >= WIN) s_acc[nj][3] = -1e30f;
        }
        float mx_lo = -1e30f, mx_hi = -1e30f;
#pragma unroll
        for (int nj = 0; nj < 8; nj++) {
            mx_lo = fmaxf(mx_lo, fmaxf(s_acc[nj][0], s_acc[nj][1]));
            mx_hi = fmaxf(mx_hi, fmaxf(s_acc[nj][2], s_acc[nj][3]));
        }
        mx_lo = fmaxf(mx_lo, __shfl_xor_sync(0xffffffffu, mx_lo, 1));
        mx_lo = fmaxf(mx_lo, __shfl_xor_sync(0xffffffffu, mx_lo, 2));
        mx_hi = fmaxf(mx_hi, __shfl_xor_sync(0xffffffffu, mx_hi, 1));
        mx_hi = fmaxf(mx_hi, __shfl_xor_sync(0xffffffffu, mx_hi, 2));

        float mn_lo = fmaxf(m_lo, mx_lo);
        float mn_hi = fmaxf(m_hi, mx_hi);
        float f_lo = __expf(m_lo - mn_lo);
        float f_hi = __expf(m_hi - mn_hi);
        m_lo = mn_lo; m_hi = mn_hi;

        float sum_lo = 0.f, sum_hi = 0.f;
#pragma unroll
        for (int nj = 0; nj < 8; nj++) {
            float p0 = __expf(s_acc[nj][0] - mn_lo);
            float p1 = __expf(s_acc[nj][1] - mn_lo);
            float p2 = __expf(s_acc[nj][2] - mn_hi);
            float p3 = __expf(s_acc[nj][3] - mn_hi);
            sum_lo += p0 + p1;
            sum_hi += p2 + p3;
            __nv_bfloat16 h0, h1, h2, h3, l0, l1, l2, l3;
            split1(p0, h0, l0); split1(p1, h1, l1);
            split1(p2, h2, l2); split1(p3, h3, l3);
            int co = nj * 8 + cq;
            *(__nv_bfloat162*)(smb + S_PH + (wid * 16 + rl) * AP_STR + co)     = __nv_bfloat162(h0, h1);
            *(__nv_bfloat162*)(smb + S_PL + (wid * 16 + rl) * AP_STR + co)     = __nv_bfloat162(l0, l1);
            *(__nv_bfloat162*)(smb + S_PH + (wid * 16 + rl + 8) * AP_STR + co) = __nv_bfloat162(h2, h3);
            *(__nv_bfloat162*)(smb + S_PL + (wid * 16 + rl + 8) * AP_STR + co) = __nv_bfloat162(l2, l3);
        }
        sum_lo += __shfl_xor_sync(0xffffffffu, sum_lo, 1);
        sum_lo += __shfl_xor_sync(0xffffffffu, sum_lo, 2);
        sum_hi += __shfl_xor_sync(0xffffffffu, sum_hi, 1);
        sum_hi += __shfl_xor_sync(0xffffffffu, sum_hi, 2);
        l_lo = l_lo * f_lo + sum_lo;
        l_hi = l_hi * f_hi + sum_hi;

#pragma unroll
        for (int nj = 0; nj < 16; nj++) {
            o_acc[nj][0] *= f_lo; o_acc[nj][1] *= f_lo;
            o_acc[nj][2] *= f_hi; o_acc[nj][3] *= f_hi;
        }
        __syncwarp();

#pragma unroll
        for (int kc = 0; kc < 4; kc++) {
            uint32_t ph_f[4], pl_f[4];
            uint32_t ap = s_base + (uint32_t)((a_row * AP_STR + kc * 16 + a_kof) * 2);
            LDSM4(ph_f, ap + S_PH * 2);
            LDSM4(pl_f, ap + S_PL * 2);
#pragma unroll
            for (int nb2 = 0; nb2 < 8; nb2 += 2) {
                uint32_t vh0[4], vl0[4], vh1[4], vl1[4];
                uint32_t av0 = s_base + (uint32_t)(((kc * 16 + v_row) * AQ_STR + (nb2)     * 16 + v_col) * 2);
                uint32_t av1 = s_base + (uint32_t)(((kc * 16 + v_row) * AQ_STR + (nb2 + 1) * 16 + v_col) * 2);
                LDSM4T(vh0, av0 + S_VH * 2);
                LDSM4T(vl0, av0 + S_VL * 2);
                LDSM4T(vh1, av1 + S_VH * 2);
                LDSM4T(vl1, av1 + S_VL * 2);
                const int a0 = nb2 * 2;
                MMA16816(o_acc[a0 + 0], ph_f, vh0[0], vh0[1]);
                MMA16816(o_acc[a0 + 1], ph_f, vh0[2], vh0[3]);
                MMA16816(o_acc[a0 + 2], ph_f, vh1[0], vh1[1]);
                MMA16816(o_acc[a0 + 3], ph_f, vh1[2], vh1[3]);
                MMA16816(o_acc[a0 + 0], ph_f, vl0[0], vl0[1]);
                MMA16816(o_acc[a0 + 1], ph_f, vl0[2], vl0[3]);
                MMA16816(o_acc[a0 + 2], ph_f, vl1[0], vl1[1]);
                MMA16816(o_acc[a0 + 3], ph_f, vl1[2], vl1[3]);
                MMA16816(o_acc[a0 + 0], pl_f, vh0[0], vh0[1]);
                MMA16816(o_acc[a0 + 1], pl_f, vh0[2], vh0[3]);
                MMA16816(o_acc[a0 + 2], pl_f, vh1[0], vh1[1]);
                MMA16816(o_acc[a0 + 3], pl_f, vh1[2], vh1[3]);
            }
        }
    }

    // ---- epilogue: O / l -> split hi/lo bf16 directly (feeds wo GEMM) ----
    float inv_lo = 1.0f / l_lo;
    float inv_hi = 1.0f / l_hi;
    const int i_lo = iw + rl;
#pragma unroll
    for (int nj = 0; nj < 16; nj++) {
        int col = nj * 8 + cq;
        size_t o0 = ((size_t)(b * SEQ + i_lo)     * HQ + h) * HDIM + col;
        size_t o1 = ((size_t)(b * SEQ + i_lo + 8) * HQ + h) * HDIM + col;
        float v0 = o_acc[nj][0] * inv_lo, v1 = o_acc[nj][1] * inv_lo;
        float v2 = o_acc[nj][2] * inv_hi, v3 = o_acc[nj][3] * inv_hi;
        __nv_bfloat16 h0, h1, h2, h3, l0, l1, l2, l3;
        split1(v0, h0, l0); split1(v1, h1, l1);
        split1(v2, h2, l2); split1(v3, h3, l3);
        *(__nv_bfloat162*)(oh + o0) = __nv_bfloat162(h0, h1);
        *(__nv_bfloat162*)(ol + o0) = __nv_bfloat162(l0, l1);
        *(__nv_bfloat162*)(oh + o1) = __nv_bfloat162(h2, h3);
        *(__nv_bfloat162*)(ol + o1) = __nv_bfloat162(l2, l3);
    }
}

// ================= launch =================
extern "C" void kernel_launch(void* const* d_in, const int* in_sizes, int n_in,
                              void* d_out, int out_size)
{
    (void)in_sizes; (void)n_in; (void)out_size;
    const float* x  = (const float*)d_in[0];
    const float* cs = (const float*)d_in[1];
    const float* sn = (const float*)d_in[2];
    const float* wq = (const float*)d_in[3];
    const float* wk = (const float*)d_in[4];
    const float* wv = (const float*)d_in[5];
    const float* wo = (const float*)d_in[6];
    float* out = (float*)d_out;

    float *qp, *kp, *vp;
    __nv_bfloat16 *ahp, *alp, *whp, *wlp;
    cudaGetSymbolAddress((void**)&qp,  g_q);
    cudaGetSymbolAddress((void**)&kp,  g_k);
    cudaGetSymbolAddress((void**)&vp,  g_v);
    cudaGetSymbolAddress((void**)&ahp, g_a_hi);
    cudaGetSymbolAddress((void**)&alp, g_a_lo);
    cudaGetSymbolAddress((void**)&whp, g_w_hi);
    cudaGetSymbolAddress((void**)&wlp, g_w_lo);

    cudaFuncSetAttribute(gemm_mma, cudaFuncAttributeMaxDynamicSharedMemorySize, GEMM_SMEM);
    cudaFuncSetAttribute(attn_mma, cudaFuncAttributeMaxDynamicSharedMemorySize, ATTN_SMEM);

    const int NELEM = T_TOK * DIMV;
    dim3 cvtb(32, 8);

    // x -> hi/lo
    cvt_split<<<(NELEM / 4) / 256, 256>>>(x, ahp, alp);

    // Q = x @ wq
    cvt_wt<<<dim3((HQ * HDIM) / 32, DIMV / 32), cvtb>>>(wq, whp, wlp, DIMV, HQ * HDIM);
    gemm_mma<<<dim3((HQ * HDIM) / 128, T_TOK / 128), 256, GEMM_SMEM>>>(
        ahp, alp, whp, wlp, qp, DIMV, HQ * HDIM);

    // K = x @ wk
    cvt_wt<<<dim3((KVH * HDIM) / 32, DIMV / 32), cvtb>>>(wk, whp, wlp, DIMV, KVH * HDIM);
    gemm_mma<<<dim3((KVH * HDIM) / 128, T_TOK / 128), 256, GEMM_SMEM>>>(
        ahp, alp, whp, wlp, kp, DIMV, KVH * HDIM);

    // V = x @ wv
    cvt_wt<<<dim3((KVH * HDIM) / 32, DIMV / 32), cvtb>>>(wv, whp, wlp, DIMV, KVH * HDIM);
    gemm_mma<<<dim3((KVH * HDIM) / 128, T_TOK / 128), 256, GEMM_SMEM>>>(
        ahp, alp, whp, wlp, vp, DIMV, KVH * HDIM);

    // RoPE
    rope_kernel<<<(T_TOK * HQ  * 64) / 256, 256>>>(qp, cs, sn, HQ);
    rope_kernel<<<(T_TOK * KVH * 64) / 256, 256>>>(kp, cs, sn, KVH);

    // attention (HMMA) -> writes split hi/lo directly
    attn_mma<<<dim3(SEQ / 128, HQ, BATCH), 256, ATTN_SMEM>>>(qp, kp, vp, ahp, alp);

    // out = ao @ wo
    cvt_wt<<<dim3(DIMV / 32, (HQ * HDIM) / 32), cvtb>>>(wo, whp, wlp, HQ * HDIM, DIMV);
    gemm_mma<<<dim3(DIMV / 128, T_TOK / 128), 256, GEMM_SMEM>>>(
        ahp, alp, whp, wlp, out, HQ * HDIM, DIMV);
}

// round 13
// speedup vs baseline: 1.2052x; 1.0162x over previous
#include <cuda_runtime.h>
#include <cuda_bf16.h>
#include <cstdint>

// ---------------- problem constants ----------------
#define T_TOK 4096
#define DIMV  4096
#define HQ    32
#define KVH   8
#define HDIM  128
#define BATCH 2
#define SEQ   2048
#define WIN   1024
#define NQKV  6144          // 4096 q + 1024 k + 1024 v

// ---------------- scratch (device globals) ----------------
__device__ float g_qkv[(size_t)T_TOK * NQKV];                 // fused q|k|v, 100 MB
__device__ __nv_bfloat16 g_a_hi[(size_t)4096 * 4096];
__device__ __nv_bfloat16 g_a_lo[(size_t)4096 * 4096];
__device__ __nv_bfloat16 g_w_hi[(size_t)NQKV * 4096];         // transposed weights [N,K]
__device__ __nv_bfloat16 g_w_lo[(size_t)NQKV * 4096];

typedef unsigned long long ull;

// ---------------- helpers ----------------
__device__ __forceinline__ uint32_t smem_u32(const void* p) {
    uint32_t a;
    asm("{ .reg .u64 t; cvta.to.shared.u64 t, %1; cvt.u32.u64 %0, t; }" : "=r"(a) : "l"(p));
    return a;
}

#define LDSM4(r, addr) \
    asm volatile("ldmatrix.sync.aligned.m8n8.x4.shared.b16 {%0,%1,%2,%3}, [%4];" \
        : "=r"((r)[0]), "=r"((r)[1]), "=r"((r)[2]), "=r"((r)[3]) : "r"(addr))

#define LDSM4T(r, addr) \
    asm volatile("ldmatrix.sync.aligned.m8n8.x4.trans.shared.b16 {%0,%1,%2,%3}, [%4];" \
        : "=r"((r)[0]), "=r"((r)[1]), "=r"((r)[2]), "=r"((r)[3]) : "r"(addr))

#define MMA16816(d, a, b0_, b1_) \
    asm volatile("mma.sync.aligned.m16n8k16.row.col.f32.bf16.bf16.f32 " \
        "{%0,%1,%2,%3}, {%4,%5,%6,%7}, {%8,%9}, {%0,%1,%2,%3};" \
        : "+f"((d)[0]), "+f"((d)[1]), "+f"((d)[2]), "+f"((d)[3]) \
        : "r"((a)[0]), "r"((a)[1]), "r"((a)[2]), "r"((a)[3]), "r"(b0_), "r"(b1_))

#define CP16(s, g) \
    asm volatile("cp.async.cg.shared.global [%0], [%1], 16;" :: "r"(s), "l"(g) : "memory")
#define CP_COMMIT() asm volatile("cp.async.commit_group;" ::: "memory")
#define CP_WAIT0()  asm volatile("cp.async.wait_group 0;" ::: "memory")

// split one fp32 into hi/lo bf16
__device__ __forceinline__ void split1(float v, __nv_bfloat16& h, __nv_bfloat16& l) {
    h = __float2bfloat16(v);
    l = __float2bfloat16(v - __bfloat162float(h));
}
__device__ __forceinline__ void split4_store(__nv_bfloat16* hp, __nv_bfloat16* lp, float4 v) {
    __nv_bfloat16 h0, h1, h2, h3, l0, l1, l2, l3;
    split1(v.x, h0, l0); split1(v.y, h1, l1);
    split1(v.z, h2, l2); split1(v.w, h3, l3);
    *(__nv_bfloat162*)(hp)     = __nv_bfloat162(h0, h1);
    *(__nv_bfloat162*)(hp + 2) = __nv_bfloat162(h2, h3);
    *(__nv_bfloat162*)(lp)     = __nv_bfloat162(l0, l1);
    *(__nv_bfloat162*)(lp + 2) = __nv_bfloat162(l2, l3);
}

// ================= conversion kernels =================
__global__ void cvt_split(const float* __restrict__ s,
                          __nv_bfloat16* __restrict__ h, __nv_bfloat16* __restrict__ l)
{
    size_t i = ((size_t)blockIdx.x * blockDim.x + threadIdx.x) * 4;
    float4 v = *(const float4*)(s + i);
    split4_store(h + i, l + i, v);
}

// generic: W[K,N] fp32 -> Wt[N,K] hi/lo bf16. block (32,8), grid (N/32, K/32). K==4096
__global__ void cvt_wt(const float* __restrict__ w,
                       __nv_bfloat16* __restrict__ th, __nv_bfloat16* __restrict__ tl,
                       int K, int N)
{
    __shared__ float t[32][33];
    int n0 = blockIdx.x * 32, k0 = blockIdx.y * 32;
    int tx = threadIdx.x, ty = threadIdx.y;
#pragma unroll
    for (int j = 0; j < 4; j++)
        t[ty + 8 * j][tx] = w[(size_t)(k0 + ty + 8 * j) * N + n0 + tx];
    __syncthreads();
#pragma unroll
    for (int j = 0; j < 4; j++) {
        float v = t[tx][ty + 8 * j];
        __nv_bfloat16 h, l;
        split1(v, h, l);
        size_t o = (size_t)(n0 + ty + 8 * j) * K + k0 + tx;
        th[o] = h; tl[o] = l;
    }
}

// fused qkv weights: wq[4096,4096] | wk[4096,1024] | wv[4096,1024] -> Wt[6144,4096]
__global__ void cvt_wt_qkv(const float* __restrict__ wq, const float* __restrict__ wk,
                           const float* __restrict__ wv,
                           __nv_bfloat16* __restrict__ th, __nv_bfloat16* __restrict__ tl)
{
    __shared__ float t[32][33];
    int n0 = blockIdx.x * 32, k0 = blockIdx.y * 32;
    int tx = threadIdx.x, ty = threadIdx.y;
    const float* w; int sn, sN;
    if (n0 < 4096)      { w = wq; sn = n0;        sN = 4096; }
    else if (n0 < 5120) { w = wk; sn = n0 - 4096; sN = 1024; }
    else                { w = wv; sn = n0 - 5120; sN = 1024; }
#pragma unroll
    for (int j = 0; j < 4; j++)
        t[ty + 8 * j][tx] = w[(size_t)(k0 + ty + 8 * j) * sN + sn + tx];
    __syncthreads();
#pragma unroll
    for (int j = 0; j < 4; j++) {
        float v = t[tx][ty + 8 * j];
        __nv_bfloat16 h, l;
        split1(v, h, l);
        size_t o = (size_t)(n0 + ty + 8 * j) * 4096 + k0 + tx;
        th[o] = h; tl[o] = l;
    }
}

// ================= HMMA GEMM: BM=64, BN=128, 128 thr, cp.async 2-stage, 3 CTAs/SM =================
#define ROWP 40
#define AL_OFF (64 * ROWP)              // 2560
#define BH_OFF (2 * 64 * ROWP)          // 5120
#define BL_OFF (BH_OFF + 128 * ROWP)    // 10240
#define STAGE_ELEM (BL_OFF + 128 * ROWP) // 15360
#define GEMM_SMEM (2 * STAGE_ELEM * 2)   // 61440 bytes

__global__ __launch_bounds__(128, 3) void gemm_mma(
    const __nv_bfloat16* __restrict__ ah, const __nv_bfloat16* __restrict__ al,
    const __nv_bfloat16* __restrict__ bh, const __nv_bfloat16* __restrict__ bl,
    float* __restrict__ C, int K, int N)
{
    extern __shared__ __nv_bfloat16 sm[];
    const uint32_t s_base = smem_u32(sm);

    const int tid  = threadIdx.x;
    const int wid  = tid >> 5;
    const int lane = tid & 31;
    const int bm   = blockIdx.y * 64;
    const int bn   = blockIdx.x * 128;
    const int m_off = (wid & 1) * 32;
    const int n_off = (wid >> 1) * 64;

    const int rr = tid >> 2;            // 0..31
    const int lc = (tid & 3) * 8;

    const int a_row = m_off + (lane & 15);
    const int a_kof = (lane >> 4) * 8;
    const int b_n   = n_off + ((lane >> 4) << 3) + (lane & 7);
    const int b_k   = ((lane >> 3) & 1) * 8;

    float acc[2][8][4];
#pragma unroll
    for (int mi = 0; mi < 2; mi++)
#pragma unroll
        for (int nj = 0; nj < 8; nj++)
#pragma unroll
            for (int u = 0; u < 4; u++) acc[mi][nj][u] = 0.f;

    const int NIT = K >> 5;

    auto CPA = [&](int it) {
        uint32_t base = s_base + (uint32_t)((it & 1) * STAGE_ELEM * 2);
        size_t k0 = (size_t)it << 5;
#pragma unroll
        for (int p = 0; p < 2; p++) {           // A hi/lo: 64 rows
            int r = rr + p * 32;
            uint32_t o = (uint32_t)((r * ROWP + lc) * 2);
            size_t oa = (size_t)(bm + r) * K + k0 + lc;
            CP16(base + o,              ah + oa);
            CP16(base + AL_OFF * 2 + o, al + oa);
        }
#pragma unroll
        for (int p = 0; p < 4; p++) {           // B hi/lo: 128 rows
            int r = rr + p * 32;
            uint32_t o = (uint32_t)((r * ROWP + lc) * 2);
            size_t ob = (size_t)(bn + r) * K + k0 + lc;
            CP16(base + BH_OFF * 2 + o, bh + ob);
            CP16(base + BL_OFF * 2 + o, bl + ob);
        }
        CP_COMMIT();
    };

    CPA(0);

    for (int it = 0; it < NIT; it++) {
        CP_WAIT0();
        __syncthreads();
        if (it + 1 < NIT) CPA(it + 1);

        const uint32_t sbuf = s_base + (uint32_t)((it & 1) * STAGE_ELEM * 2);
#pragma unroll
        for (int ks = 0; ks < 2; ks++) {
            uint32_t ahf[2][4], alf[2][4];
            {
                uint32_t r0 = sbuf + (uint32_t)((a_row * ROWP + ks * 16 + a_kof) * 2);
                uint32_t r1 = r0 + 16 * ROWP * 2;
                LDSM4(ahf[0], r0);
                LDSM4(ahf[1], r1);
                LDSM4(alf[0], r0 + AL_OFF * 2);
                LDSM4(alf[1], r1 + AL_OFF * 2);
            }
#pragma unroll
            for (int p = 0; p < 4; p++) {
                uint32_t bb = sbuf + (uint32_t)(BH_OFF * 2) +
                              (uint32_t)(((b_n + p * 16) * ROWP + ks * 16 + b_k) * 2);
                uint32_t bhf[4], blf[4];
                LDSM4(bhf, bb);
                LDSM4(blf, bb + (BL_OFF - BH_OFF) * 2);
                const int nj0 = p * 2;
                MMA16816(acc[0][nj0],     ahf[0], bhf[0], bhf[1]);
                MMA16816(acc[0][nj0 + 1], ahf[0], bhf[2], bhf[3]);
                MMA16816(acc[1][nj0],     ahf[1], bhf[0], bhf[1]);
                MMA16816(acc[1][nj0 + 1], ahf[1], bhf[2], bhf[3]);
                MMA16816(acc[0][nj0],     ahf[0], blf[0], blf[1]);
                MMA16816(acc[0][nj0 + 1], ahf[0], blf[2], blf[3]);
                MMA16816(acc[1][nj0],     ahf[1], blf[0], blf[1]);
                MMA16816(acc[1][nj0 + 1], ahf[1], blf[2], blf[3]);
                MMA16816(acc[0][nj0],     alf[0], bhf[0], bhf[1]);
                MMA16816(acc[0][nj0 + 1], alf[0], bhf[2], bhf[3]);
                MMA16816(acc[1][nj0],     alf[1], bhf[0], bhf[1]);
                MMA16816(acc[1][nj0 + 1], alf[1], bhf[2], bhf[3]);
            }
        }
        __syncthreads();
    }

    const int eg = lane >> 2, et = lane & 3;
#pragma unroll
    for (int mi = 0; mi < 2; mi++)
#pragma unroll
    for (int nj = 0; nj < 8; nj++) {
        float* c = C + (size_t)(bm + m_off + mi * 16 + eg) * N + bn + n_off + nj * 8 + et * 2;
        *(float2*)c                   = make_float2(acc[mi][nj][0], acc[mi][nj][1]);
        *(float2*)(c + (size_t)8 * N) = make_float2(acc[mi][nj][2], acc[mi][nj][3]);
    }
}

// ================= RoPE (strided, for fused qkv buffer) =================
__global__ void rope_kernel(float* __restrict__ t, const float* __restrict__ cs,
                            const float* __restrict__ sn, int heads, int rstride)
{
    int idx = blockIdx.x * blockDim.x + threadIdx.x;
    int i   = idx & 63;
    int h   = (idx >> 6) % heads;
    int tok = idx / (64 * heads);
    float c = cs[tok * 64 + i];
    float s = sn[tok * 64 + i];
    float* p = t + (size_t)tok * rstride + h * HDIM + 2 * i;
    float t0 = p[0], t1 = p[1];
    p[0] = t0 * c - t1 * s;
    p[1] = t0 * s + t1 * c;
}

// ================= HMMA windowed flash attention (reads fused qkv) =================
#define AQ_STR 136
#define AP_STR 72
#define S_QH 0
#define S_QL (128 * AQ_STR)
#define S_KH (2 * 128 * AQ_STR)
#define S_KL (S_KH + 64 * AQ_STR)
#define S_VH (S_KL + 64 * AQ_STR)
#define S_VL (S_VH + 64 * AQ_STR)
#define S_PH (S_VL + 64 * AQ_STR)
#define S_PL (S_PH + 128 * AP_STR)
#define ATTN_ELEM (S_PL + 128 * AP_STR)
#define ATTN_SMEM (ATTN_ELEM * 2)

__global__ __launch_bounds__(256) void attn_mma(
    const float* __restrict__ qkv,
    __nv_bfloat16* __restrict__ oh, __nv_bfloat16* __restrict__ ol)
{
    extern __shared__ __nv_bfloat16 smb[];
    const uint32_t s_base = smem_u32(smb);

    const int tid  = threadIdx.x;
    const int wid  = tid >> 5;
    const int lane = tid & 31;
    const int h    = blockIdx.y;
    const int b    = blockIdx.z;
    const int kvh  = h >> 2;
    const int i0   = blockIdx.x * 128;
    const int qb2  = blockIdx.x * 2;
    const int tok0 = b * SEQ + i0;

    const float scale = 0.08838834764831845f;

    for (int i = tid; i < 128 * 32; i += 256) {
        int r = i >> 5, c = (i & 31) * 4;
        float4 vq = *(const float4*)(qkv + (size_t)(tok0 + r) * NQKV + h * HDIM + c);
        vq.x *= scale; vq.y *= scale; vq.z *= scale; vq.w *= scale;
        split4_store(smb + S_QH + r * AQ_STR + c, smb + S_QL + r * AQ_STR + c, vq);
    }

    const int iw    = i0 + wid * 16;
    const int rl    = lane >> 2;
    const int cq    = (lane & 3) * 2;
    const int a_row = wid * 16 + (lane & 15);
    const int a_kof = (lane >> 4) * 8;
    const int kb_r  = ((lane >> 4) << 3) + (lane & 7);
    const int kb_k  = ((lane >> 3) & 1) * 8;
    const int v_row = lane & 15;
    const int v_col = (lane >> 4) * 8;

    float m_lo = -1e30f, m_hi = -1e30f, l_lo = 0.f, l_hi = 0.f;
    float o_acc[16][4];
#pragma unroll
    for (int nj = 0; nj < 16; nj++)
#pragma unroll
        for (int u = 0; u < 4; u++) o_acc[nj][u] = 0.f;

    int jb_lo = qb2 - 16; if (jb_lo < 0) jb_lo = 0;
    const int jb_hi = qb2 + 1;

    for (int jb = jb_lo; jb <= jb_hi; jb++) {
        const int j0 = jb * 64;
        __syncthreads();

        for (int i = tid; i < 64 * 32; i += 256) {
            int r = i >> 5, c = (i & 31) * 4;
            size_t off = (size_t)(b * SEQ + j0 + r) * NQKV + kvh * HDIM + c;
            float4 kk = *(const float4*)(qkv + 4096 + off);
            float4 vv = *(const float4*)(qkv + 5120 + off);
            split4_store(smb + S_KH + r * AQ_STR + c, smb + S_KL + r * AQ_STR + c, kk);
            split4_store(smb + S_VH + r * AQ_STR + c, smb + S_VL + r * AQ_STR + c, vv);
        }
        __syncthreads();

        if (j0 > iw + 15 || j0 + 63 < iw - (WIN - 1)) continue;

        float s_acc[8][4];
#pragma unroll
        for (int nj = 0; nj < 8; nj++)
#pragma unroll
            for (int u = 0; u < 4; u++) s_acc[nj][u] = 0.f;

#pragma unroll
        for (int ks = 0; ks < 8; ks++) {
            uint32_t qh_f[4], ql_f[4];
            uint32_t aq = s_base + (uint32_t)((a_row * AQ_STR + ks * 16 + a_kof) * 2);
            LDSM4(qh_f, aq + S_QH * 2);
            LDSM4(ql_f, aq + S_QL * 2);
#pragma unroll
            for (int kp2 = 0; kp2 < 4; kp2 += 2) {
                uint32_t kh0[4], kl0[4], kh1[4], kl1[4];
                uint32_t ab0 = s_base + (uint32_t)((((kp2)     * 16 + kb_r) * AQ_STR + ks * 16 + kb_k) * 2);
                uint32_t ab1 = s_base + (uint32_t)((((kp2 + 1) * 16 + kb_r) * AQ_STR + ks * 16 + kb_k) * 2);
                LDSM4(kh0, ab0 + S_KH * 2);
                LDSM4(kl0, ab0 + S_KL * 2);
                LDSM4(kh1, ab1 + S_KH * 2);
                LDSM4(kl1, ab1 + S_KL * 2);
                const int a0 = kp2 * 2;
                MMA16816(s_acc[a0 + 0], qh_f, kh0[0], kh0[1]);
                MMA16816(s_acc[a0 + 1], qh_f, kh0[2], kh0[3]);
                MMA16816(s_acc[a0 + 2], qh_f, kh1[0], kh1[1]);
                MMA16816(s_acc[a0 + 3], qh_f, kh1[2], kh1[3]);
                MMA16816(s_acc[a0 + 0], qh_f, kl0[0], kl0[1]);
                MMA16816(s_acc[a0 + 1], qh_f, kl0[2], kl0[3]);
                MMA16816(s_acc[a0 + 2], qh_f, kl1[0], kl1[1]);
                MMA16816(s_acc[a0 + 3], qh_f, kl1[2], kl1[3]);
                MMA16816(s_acc[a0 + 0], ql_f, kh0[0], kh0[1]);
                MMA16816(s_acc[a0 + 1], ql_f, kh0[2], kh0[3]);
                MMA16816(s_acc[a0 + 2], ql_f, kh1[0], kh1[1]);
                MMA16816(s_acc[a0 + 3], ql_f, kh1[2], kh1[3]);
            }
        }

        const int i_lo = iw + rl;
        const int i_hi = i_lo + 8;
#pragma unroll
        for (int nj = 0; nj < 8; nj++) {
            int jg = j0 + nj * 8 + cq;
            if (jg     > i_lo || i_lo - jg     >= WIN) s_acc[nj][0] = -1e30f;
            if (jg + 1 > i_lo || i_lo - jg - 1 >= WIN) s_acc[nj][1] = -1e30f;
            if (jg     > i_hi || i_hi - jg     >= WIN) s_acc[nj][2] = -1e30f;
            if (jg + 1 > i_hi || i_hi - jg - 1 >= WIN) s_acc[nj][3] = -1e30f;
        }
        float mx_lo = -1e30f, mx_hi = -1e30f;
#pragma unroll
        for (int nj = 0; nj < 8; nj++) {
            mx_lo = fmaxf(mx_lo, fmaxf(s_acc[nj][0], s_acc[nj][1]));
            mx_hi = fmaxf(mx_hi, fmaxf(s_acc[nj][2], s_acc[nj][3]));
        }
        mx_lo = fmaxf(mx_lo, __shfl_xor_sync(0xffffffffu, mx_lo, 1));
        mx_lo = fmaxf(mx_lo, __shfl_xor_sync(0xffffffffu, mx_lo, 2));
        mx_hi = fmaxf(mx_hi, __shfl_xor_sync(0xffffffffu, mx_hi, 1));
        mx_hi = fmaxf(mx_hi, __shfl_xor_sync(0xffffffffu, mx_hi, 2));

        float mn_lo = fmaxf(m_lo, mx_lo);
        float mn_hi = fmaxf(m_hi, mx_hi);
        float f_lo = __expf(m_lo - mn_lo);
        float f_hi = __expf(m_hi - mn_hi);
        m_lo = mn_lo; m_hi = mn_hi;

        float sum_lo = 0.f, sum_hi = 0.f;
#pragma unroll
        for (int nj = 0; nj < 8; nj++) {
            float p0 = __expf(s_acc[nj][0] - mn_lo);
            float p1 = __expf(s_acc[nj][1] - mn_lo);
            float p2 = __expf(s_acc[nj][2] - mn_hi);
            float p3 = __expf(s_acc[nj][3] - mn_hi);
            sum_lo += p0 + p1;
            sum_hi += p2 + p3;
            __nv_bfloat16 h0, h1, h2, h3, l0, l1, l2, l3;
            split1(p0, h0, l0); split1(p1, h1, l1);
            split1(p2, h2, l2); split1(p3, h3, l3);
            int co = nj * 8 + cq;
            *(__nv_bfloat162*)(smb + S_PH + (wid * 16 + rl) * AP_STR + co)     = __nv_bfloat162(h0, h1);
            *(__nv_bfloat162*)(smb + S_PL + (wid * 16 + rl) * AP_STR + co)     = __nv_bfloat162(l0, l1);
            *(__nv_bfloat162*)(smb + S_PH + (wid * 16 + rl + 8) * AP_STR + co) = __nv_bfloat162(h2, h3);
            *(__nv_bfloat162*)(smb + S_PL + (wid * 16 + rl + 8) * AP_STR + co) = __nv_bfloat162(l2, l3);
        }
        sum_lo += __shfl_xor_sync(0xffffffffu, sum_lo, 1);
        sum_lo += __shfl_xor_sync(0xffffffffu, sum_lo, 2);
        sum_hi += __shfl_xor_sync(0xffffffffu, sum_hi, 1);
        sum_hi += __shfl_xor_sync(0xffffffffu, sum_hi, 2);
        l_lo = l_lo * f_lo + sum_lo;
        l_hi = l_hi * f_hi + sum_hi;

#pragma unroll
        for (int nj = 0; nj < 16; nj++) {
            o_acc[nj][0] *= f_lo; o_acc[nj][1] *= f_lo;
            o_acc[nj][2] *= f_hi; o_acc[nj][3] *= f_hi;
        }
        __syncwarp();

#pragma unroll
        for (int kc = 0; kc < 4; kc++) {
            uint32_t ph_f[4], pl_f[4];
            uint32_t ap = s_base + (uint32_t)((a_row * AP_STR + kc * 16 + a_kof) * 2);
            LDSM4(ph_f, ap + S_PH * 2);
            LDSM4(pl_f, ap + S_PL * 2);
#pragma unroll
            for (int nb2 = 0; nb2 < 8; nb2 += 2) {
                uint32_t vh0[4], vl0[4], vh1[4], vl1[4];
                uint32_t av0 = s_base + (uint32_t)(((kc * 16 + v_row) * AQ_STR + (nb2)     * 16 + v_col) * 2);
                uint32_t av1 = s_base + (uint32_t)(((kc * 16 + v_row) * AQ_STR + (nb2 + 1) * 16 + v_col) * 2);
                LDSM4T(vh0, av0 + S_VH * 2);
                LDSM4T(vl0, av0 + S_VL * 2);
                LDSM4T(vh1, av1 + S_VH * 2);
                LDSM4T(vl1, av1 + S_VL * 2);
                const int a0 = nb2 * 2;
                MMA16816(o_acc[a0 + 0], ph_f, vh0[0], vh0[1]);
                MMA16816(o_acc[a0 + 1], ph_f, vh0[2], vh0[3]);
                MMA16816(o_acc[a0 + 2], ph_f, vh1[0], vh1[1]);
                MMA16816(o_acc[a0 + 3], ph_f, vh1[2], vh1[3]);
                MMA16816(o_acc[a0 + 0], ph_f, vl0[0], vl0[1]);
                MMA16816(o_acc[a0 + 1], ph_f, vl0[2], vl0[3]);
                MMA16816(o_acc[a0 + 2], ph_f, vl1[0], vl1[1]);
                MMA16816(o_acc[a0 + 3], ph_f, vl1[2], vl1[3]);
                MMA16816(o_acc[a0 + 0], pl_f, vh0[0], vh0[1]);
                MMA16816(o_acc[a0 + 1], pl_f, vh0[2], vh0[3]);
                MMA16816(o_acc[a0 + 2], pl_f, vh1[0], vh1[1]);
                MMA16816(o_acc[a0 + 3], pl_f, vh1[2], vh1[3]);
            }
        }
    }

    float inv_lo = 1.0f / l_lo;
    float inv_hi = 1.0f / l_hi;
    const int i_lo = iw + rl;
#pragma unroll
    for (int nj = 0; nj < 16; nj++) {
        int col = nj * 8 + cq;
        size_t o0 = ((size_t)(b * SEQ + i_lo)     * HQ + h) * HDIM + col;
        size_t o1 = ((size_t)(b * SEQ + i_lo + 8) * HQ + h) * HDIM + col;
        float v0 = o_acc[nj][0] * inv_lo, v1 = o_acc[nj][1] * inv_lo;
        float v2 = o_acc[nj][2] * inv_hi, v3 = o_acc[nj][3] * inv_hi;
        __nv_bfloat16 h0, h1, h2, h3, l0, l1, l2, l3;
        split1(v0, h0, l0); split1(v1, h1, l1);
        split1(v2, h2, l2); split1(v3, h3, l3);
        *(__nv_bfloat162*)(oh + o0) = __nv_bfloat162(h0, h1);
        *(__nv_bfloat162*)(ol + o0) = __nv_bfloat162(l0, l1);
        *(__nv_bfloat162*)(oh + o1) = __nv_bfloat162(h2, h3);
        *(__nv_bfloat162*)(ol + o1) = __nv_bfloat162(l2, l3);
    }
}

// ================= launch =================
extern "C" void kernel_launch(void* const* d_in, const int* in_sizes, int n_in,
                              void* d_out, int out_size)
{
    (void)in_sizes; (void)n_in; (void)out_size;
    const float* x  = (const float*)d_in[0];
    const float* cs = (const float*)d_in[1];
    const float* sn = (const float*)d_in[2];
    const float* wq = (const float*)d_in[3];
    const float* wk = (const float*)d_in[4];
    const float* wv = (const float*)d_in[5];
    const float* wo = (const float*)d_in[6];
    float* out = (float*)d_out;

    float *qkvp;
    __nv_bfloat16 *ahp, *alp, *whp, *wlp;
    cudaGetSymbolAddress((void**)&qkvp, g_qkv);
    cudaGetSymbolAddress((void**)&ahp,  g_a_hi);
    cudaGetSymbolAddress((void**)&alp,  g_a_lo);
    cudaGetSymbolAddress((void**)&whp,  g_w_hi);
    cudaGetSymbolAddress((void**)&wlp,  g_w_lo);

    cudaFuncSetAttribute(gemm_mma, cudaFuncAttributeMaxDynamicSharedMemorySize, GEMM_SMEM);
    cudaFuncSetAttribute(attn_mma, cudaFuncAttributeMaxDynamicSharedMemorySize, ATTN_SMEM);

    const int NELEM = T_TOK * DIMV;
    dim3 cvtb(32, 8);

    // x -> hi/lo
    cvt_split<<<(NELEM / 4) / 256, 256>>>(x, ahp, alp);

    // fused qkv weights -> Wt[6144, 4096]
    cvt_wt_qkv<<<dim3(NQKV / 32, DIMV / 32), cvtb>>>(wq, wk, wv, whp, wlp);

    // qkv = x @ [wq|wk|wv]   (C is [T, 6144])
    gemm_mma<<<dim3(NQKV / 128, T_TOK / 64), 128, GEMM_SMEM>>>(
        ahp, alp, whp, wlp, qkvp, DIMV, NQKV);

    // RoPE on q (cols 0..4095) and k (cols 4096..5119), strided rows
    rope_kernel<<<(T_TOK * HQ  * 64) / 256, 256>>>(qkvp,        cs, sn, HQ,  NQKV);
    rope_kernel<<<(T_TOK * KVH * 64) / 256, 256>>>(qkvp + 4096, cs, sn, KVH, NQKV);

    // attention (HMMA) -> writes split hi/lo directly into A buffers
    attn_mma<<<dim3(SEQ / 128, HQ, BATCH), 256, ATTN_SMEM>>>(qkvp, ahp, alp);

    // out = ao @ wo
    cvt_wt<<<dim3(DIMV / 32, (HQ * HDIM) / 32), cvtb>>>(wo, whp, wlp, HQ * HDIM, DIMV);
    gemm_mma<<<dim3(DIMV / 128, T_TOK / 64), 128, GEMM_SMEM>>>(
        ahp, alp, whp, wlp, out, HQ * HDIM, DIMV);
}

// round 14
// speedup vs baseline: 1.2645x; 1.0493x over previous
#include <cuda_runtime.h>
#include <cuda_bf16.h>
#include <cstdint>

// ---------------- problem constants ----------------
#define T_TOK 4096
#define DIMV  4096
#define HQ    32
#define KVH   8
#define HDIM  128
#define BATCH 2
#define SEQ   2048
#define WIN   1024
#define NQKV  6144          // 4096 q + 1024 k + 1024 v

// ---------------- scratch (device globals) ----------------
__device__ __nv_bfloat16 g_qkv_hi[(size_t)T_TOK * NQKV];      // rope'd, scaled, split
__device__ __nv_bfloat16 g_qkv_lo[(size_t)T_TOK * NQKV];
__device__ __nv_bfloat16 g_a_hi[(size_t)4096 * 4096];         // x, then ao
__device__ __nv_bfloat16 g_a_lo[(size_t)4096 * 4096];
__device__ __nv_bfloat16 g_w_hi[(size_t)NQKV * 4096];         // transposed weights [N,K]
__device__ __nv_bfloat16 g_w_lo[(size_t)NQKV * 4096];

typedef unsigned long long ull;

// ---------------- helpers ----------------
__device__ __forceinline__ uint32_t smem_u32(const void* p) {
    uint32_t a;
    asm("{ .reg .u64 t; cvta.to.shared.u64 t, %1; cvt.u32.u64 %0, t; }" : "=r"(a) : "l"(p));
    return a;
}

#define LDSM4(r, addr) \
    asm volatile("ldmatrix.sync.aligned.m8n8.x4.shared.b16 {%0,%1,%2,%3}, [%4];" \
        : "=r"((r)[0]), "=r"((r)[1]), "=r"((r)[2]), "=r"((r)[3]) : "r"(addr))

#define LDSM4T(r, addr) \
    asm volatile("ldmatrix.sync.aligned.m8n8.x4.trans.shared.b16 {%0,%1,%2,%3}, [%4];" \
        : "=r"((r)[0]), "=r"((r)[1]), "=r"((r)[2]), "=r"((r)[3]) : "r"(addr))

#define MMA16816(d, a, b0_, b1_) \
    asm volatile("mma.sync.aligned.m16n8k16.row.col.f32.bf16.bf16.f32 " \
        "{%0,%1,%2,%3}, {%4,%5,%6,%7}, {%8,%9}, {%0,%1,%2,%3};" \
        : "+f"((d)[0]), "+f"((d)[1]), "+f"((d)[2]), "+f"((d)[3]) \
        : "r"((a)[0]), "r"((a)[1]), "r"((a)[2]), "r"((a)[3]), "r"(b0_), "r"(b1_))

#define CP16(s, g) \
    asm volatile("cp.async.cg.shared.global [%0], [%1], 16;" :: "r"(s), "l"(g) : "memory")
#define CP_COMMIT() asm volatile("cp.async.commit_group;" ::: "memory")
#define CP_WAIT0()  asm volatile("cp.async.wait_group 0;" ::: "memory")

// split one fp32 into hi/lo bf16
__device__ __forceinline__ void split1(float v, __nv_bfloat16& h, __nv_bfloat16& l) {
    h = __float2bfloat16(v);
    l = __float2bfloat16(v - __bfloat162float(h));
}
__device__ __forceinline__ void split4_store(__nv_bfloat16* hp, __nv_bfloat16* lp, float4 v) {
    __nv_bfloat16 h0, h1, h2, h3, l0, l1, l2, l3;
    split1(v.x, h0, l0); split1(v.y, h1, l1);
    split1(v.z, h2, l2); split1(v.w, h3, l3);
    *(__nv_bfloat162*)(hp)     = __nv_bfloat162(h0, h1);
    *(__nv_bfloat162*)(hp + 2) = __nv_bfloat162(h2, h3);
    *(__nv_bfloat162*)(lp)     = __nv_bfloat162(l0, l1);
    *(__nv_bfloat162*)(lp + 2) = __nv_bfloat162(l2, l3);
}

// ================= conversion kernels =================
__global__ void cvt_split(const float* __restrict__ s,
                          __nv_bfloat16* __restrict__ h, __nv_bfloat16* __restrict__ l)
{
    size_t i = ((size_t)blockIdx.x * blockDim.x + threadIdx.x) * 4;
    float4 v = *(const float4*)(s + i);
    split4_store(h + i, l + i, v);
}

// generic: W[K,N] fp32 -> Wt[N,K] hi/lo bf16. block (32,8), grid (N/32, K/32)
__global__ void cvt_wt(const float* __restrict__ w,
                       __nv_bfloat16* __restrict__ th, __nv_bfloat16* __restrict__ tl,
                       int K, int N)
{
    __shared__ float t[32][33];
    int n0 = blockIdx.x * 32, k0 = blockIdx.y * 32;
    int tx = threadIdx.x, ty = threadIdx.y;
#pragma unroll
    for (int j = 0; j < 4; j++)
        t[ty + 8 * j][tx] = w[(size_t)(k0 + ty + 8 * j) * N + n0 + tx];
    __syncthreads();
#pragma unroll
    for (int j = 0; j < 4; j++) {
        float v = t[tx][ty + 8 * j];
        __nv_bfloat16 h, l;
        split1(v, h, l);
        size_t o = (size_t)(n0 + ty + 8 * j) * K + k0 + tx;
        th[o] = h; tl[o] = l;
    }
}

// fused qkv weights: wq[4096,4096] | wk[4096,1024] | wv[4096,1024] -> Wt[6144,4096]
__global__ void cvt_wt_qkv(const float* __restrict__ wq, const float* __restrict__ wk,
                           const float* __restrict__ wv,
                           __nv_bfloat16* __restrict__ th, __nv_bfloat16* __restrict__ tl)
{
    __shared__ float t[32][33];
    int n0 = blockIdx.x * 32, k0 = blockIdx.y * 32;
    int tx = threadIdx.x, ty = threadIdx.y;
    const float* w; int sn, sN;
    if (n0 < 4096)      { w = wq; sn = n0;        sN = 4096; }
    else if (n0 < 5120) { w = wk; sn = n0 - 4096; sN = 1024; }
    else                { w = wv; sn = n0 - 5120; sN = 1024; }
#pragma unroll
    for (int j = 0; j < 4; j++)
        t[ty + 8 * j][tx] = w[(size_t)(k0 + ty + 8 * j) * sN + sn + tx];
    __syncthreads();
#pragma unroll
    for (int j = 0; j < 4; j++) {
        float v = t[tx][ty + 8 * j];
        __nv_bfloat16 h, l;
        split1(v, h, l);
        size_t o = (size_t)(n0 + ty + 8 * j) * 4096 + k0 + tx;
        th[o] = h; tl[o] = l;
    }
}

// ================= HMMA GEMM: BM=64, BN=128, 128 thr, cp.async 2-stage =================
// MODE 0: plain fp32 store to C.
// MODE 1: qkv epilogue — scale (q), rope (q,k), split hi/lo bf16 to oh/ol.
#define ROWP 40
#define AL_OFF (64 * ROWP)
#define BH_OFF (2 * 64 * ROWP)
#define BL_OFF (BH_OFF + 128 * ROWP)
#define STAGE_ELEM (BL_OFF + 128 * ROWP)
#define GEMM_SMEM (2 * STAGE_ELEM * 2)

template <int MODE>
__global__ __launch_bounds__(128, 3) void gemm_mma(
    const __nv_bfloat16* __restrict__ ah, const __nv_bfloat16* __restrict__ al,
    const __nv_bfloat16* __restrict__ bh, const __nv_bfloat16* __restrict__ bl,
    float* __restrict__ C,
    __nv_bfloat16* __restrict__ oh, __nv_bfloat16* __restrict__ ol,
    const float* __restrict__ cs, const float* __restrict__ sn,
    int K, int N)
{
    extern __shared__ __nv_bfloat16 sm[];
    const uint32_t s_base = smem_u32(sm);

    const int tid  = threadIdx.x;
    const int wid  = tid >> 5;
    const int lane = tid & 31;
    const int bm   = blockIdx.y * 64;
    const int bn   = blockIdx.x * 128;
    const int m_off = (wid & 1) * 32;
    const int n_off = (wid >> 1) * 64;

    const int rr = tid >> 2;
    const int lc = (tid & 3) * 8;

    const int a_row = m_off + (lane & 15);
    const int a_kof = (lane >> 4) * 8;
    const int b_n   = n_off + ((lane >> 4) << 3) + (lane & 7);
    const int b_k   = ((lane >> 3) & 1) * 8;

    float acc[2][8][4];
#pragma unroll
    for (int mi = 0; mi < 2; mi++)
#pragma unroll
        for (int nj = 0; nj < 8; nj++)
#pragma unroll
            for (int u = 0; u < 4; u++) acc[mi][nj][u] = 0.f;

    const int NIT = K >> 5;

    auto CPA = [&](int it) {
        uint32_t base = s_base + (uint32_t)((it & 1) * STAGE_ELEM * 2);
        size_t k0 = (size_t)it << 5;
#pragma unroll
        for (int p = 0; p < 2; p++) {
            int r = rr + p * 32;
            uint32_t o = (uint32_t)((r * ROWP + lc) * 2);
            size_t oa = (size_t)(bm + r) * K + k0 + lc;
            CP16(base + o,              ah + oa);
            CP16(base + AL_OFF * 2 + o, al + oa);
        }
#pragma unroll
        for (int p = 0; p < 4; p++) {
            int r = rr + p * 32;
            uint32_t o = (uint32_t)((r * ROWP + lc) * 2);
            size_t ob = (size_t)(bn + r) * K + k0 + lc;
            CP16(base + BH_OFF * 2 + o, bh + ob);
            CP16(base + BL_OFF * 2 + o, bl + ob);
        }
        CP_COMMIT();
    };

    CPA(0);

    for (int it = 0; it < NIT; it++) {
        CP_WAIT0();
        __syncthreads();
        if (it + 1 < NIT) CPA(it + 1);

        const uint32_t sbuf = s_base + (uint32_t)((it & 1) * STAGE_ELEM * 2);
#pragma unroll
        for (int ks = 0; ks < 2; ks++) {
            uint32_t ahf[2][4], alf[2][4];
            {
                uint32_t r0 = sbuf + (uint32_t)((a_row * ROWP + ks * 16 + a_kof) * 2);
                uint32_t r1 = r0 + 16 * ROWP * 2;
                LDSM4(ahf[0], r0);
                LDSM4(ahf[1], r1);
                LDSM4(alf[0], r0 + AL_OFF * 2);
                LDSM4(alf[1], r1 + AL_OFF * 2);
            }
#pragma unroll
            for (int p = 0; p < 4; p++) {
                uint32_t bb = sbuf + (uint32_t)(BH_OFF * 2) +
                              (uint32_t)(((b_n + p * 16) * ROWP + ks * 16 + b_k) * 2);
                uint32_t bhf[4], blf[4];
                LDSM4(bhf, bb);
                LDSM4(blf, bb + (BL_OFF - BH_OFF) * 2);
                const int nj0 = p * 2;
                MMA16816(acc[0][nj0],     ahf[0], bhf[0], bhf[1]);
                MMA16816(acc[0][nj0 + 1], ahf[0], bhf[2], bhf[3]);
                MMA16816(acc[1][nj0],     ahf[1], bhf[0], bhf[1]);
                MMA16816(acc[1][nj0 + 1], ahf[1], bhf[2], bhf[3]);
                MMA16816(acc[0][nj0],     ahf[0], blf[0], blf[1]);
                MMA16816(acc[0][nj0 + 1], ahf[0], blf[2], blf[3]);
                MMA16816(acc[1][nj0],     ahf[1], blf[0], blf[1]);
                MMA16816(acc[1][nj0 + 1], ahf[1], blf[2], blf[3]);
                MMA16816(acc[0][nj0],     alf[0], bhf[0], bhf[1]);
                MMA16816(acc[0][nj0 + 1], alf[0], bhf[2], bhf[3]);
                MMA16816(acc[1][nj0],     alf[1], bhf[0], bhf[1]);
                MMA16816(acc[1][nj0 + 1], alf[1], bhf[2], bhf[3]);
            }
        }
        __syncthreads();
    }

    const int eg = lane >> 2, et = lane & 3;

    if (MODE == 0) {
#pragma unroll
        for (int mi = 0; mi < 2; mi++)
#pragma unroll
        for (int nj = 0; nj < 8; nj++) {
            float* c = C + (size_t)(bm + m_off + mi * 16 + eg) * N + bn + n_off + nj * 8 + et * 2;
            *(float2*)c                   = make_float2(acc[mi][nj][0], acc[mi][nj][1]);
            *(float2*)(c + (size_t)8 * N) = make_float2(acc[mi][nj][2], acc[mi][nj][3]);
        }
    } else {
        // qkv epilogue: region uniform per CTA (BN=128 divides 4096/1024 boundaries)
        const int regn = (bn >= 5120) ? 2 : (bn >= 4096 ? 1 : 0);
        const float qs = 0.08838834764831845f;   // 1/sqrt(128)
#pragma unroll
        for (int mi = 0; mi < 2; mi++) {
            const int r0 = bm + m_off + mi * 16 + eg;
            const int r1 = r0 + 8;
#pragma unroll
            for (int nj = 0; nj < 8; nj++) {
                const int c = bn + n_off + nj * 8 + et * 2;
                float a0 = acc[mi][nj][0], a1 = acc[mi][nj][1];
                float b0 = acc[mi][nj][2], b1 = acc[mi][nj][3];
                if (regn == 0) { a0 *= qs; a1 *= qs; b0 *= qs; b1 *= qs; }
                if (regn < 2) {
                    const int i = (c & 127) >> 1;
                    float c0 = cs[r0 * 64 + i], s0 = sn[r0 * 64 + i];
                    float c1 = cs[r1 * 64 + i], s1 = sn[r1 * 64 + i];
                    float t0 = a0 * c0 - a1 * s0; a1 = a0 * s0 + a1 * c0; a0 = t0;
                    float t1 = b0 * c1 - b1 * s1; b1 = b0 * s1 + b1 * c1; b0 = t1;
                }
                __nv_bfloat16 h0, h1, l0, l1;
                size_t o0 = (size_t)r0 * N + c;
                size_t o1 = (size_t)r1 * N + c;
                split1(a0, h0, l0); split1(a1, h1, l1);
                *(__nv_bfloat162*)(oh + o0) = __nv_bfloat162(h0, h1);
                *(__nv_bfloat162*)(ol + o0) = __nv_bfloat162(l0, l1);
                split1(b0, h0, l0); split1(b1, h1, l1);
                *(__nv_bfloat162*)(oh + o1) = __nv_bfloat162(h0, h1);
                *(__nv_bfloat162*)(ol + o1) = __nv_bfloat162(l0, l1);
            }
        }
    }
}

// ================= HMMA windowed flash attention (pre-split bf16 qkv) =================
#define AQ_STR 136
#define AP_STR 72
#define S_QH 0
#define S_QL (128 * AQ_STR)
#define S_KH (2 * 128 * AQ_STR)
#define S_KL (S_KH + 64 * AQ_STR)
#define S_VH (S_KL + 64 * AQ_STR)
#define S_VL (S_VH + 64 * AQ_STR)
#define S_PH (S_VL + 64 * AQ_STR)
#define S_PL (S_PH + 128 * AP_STR)
#define ATTN_ELEM (S_PL + 128 * AP_STR)
#define ATTN_SMEM (ATTN_ELEM * 2)

__global__ __launch_bounds__(256) void attn_mma(
    const __nv_bfloat16* __restrict__ qh_g, const __nv_bfloat16* __restrict__ ql_g,
    __nv_bfloat16* __restrict__ oh, __nv_bfloat16* __restrict__ ol)
{
    extern __shared__ __nv_bfloat16 smb[];
    const uint32_t s_base = smem_u32(smb);

    const int tid  = threadIdx.x;
    const int wid  = tid >> 5;
    const int lane = tid & 31;
    const int h    = blockIdx.y;
    const int b    = blockIdx.z;
    const int kvh  = h >> 2;
    const int i0   = blockIdx.x * 128;
    const int qb2  = blockIdx.x * 2;
    const int tok0 = b * SEQ + i0;

    // Q tile: direct bf16 hi/lo copies via cp.async (already scaled + rope'd)
    for (int i = tid; i < 128 * 16; i += 256) {
        int r = i >> 4, ch = (i & 15) * 8;
        size_t src = (size_t)(tok0 + r) * NQKV + h * HDIM + ch;
        uint32_t dst = s_base + (uint32_t)((S_QH + r * AQ_STR + ch) * 2);
        CP16(dst,                      qh_g + src);
        CP16(dst + (S_QL - S_QH) * 2,  ql_g + src);
    }
    CP_COMMIT();

    const int iw    = i0 + wid * 16;
    const int rl    = lane >> 2;
    const int cq    = (lane & 3) * 2;
    const int a_row = wid * 16 + (lane & 15);
    const int a_kof = (lane >> 4) * 8;
    const int kb_r  = ((lane >> 4) << 3) + (lane & 7);
    const int kb_k  = ((lane >> 3) & 1) * 8;
    const int v_row = lane & 15;
    const int v_col = (lane >> 4) * 8;

    float m_lo = -1e30f, m_hi = -1e30f, l_lo = 0.f, l_hi = 0.f;
    float o_acc[16][4];
#pragma unroll
    for (int nj = 0; nj < 16; nj++)
#pragma unroll
        for (int u = 0; u < 4; u++) o_acc[nj][u] = 0.f;

    int jb_lo = qb2 - 16; if (jb_lo < 0) jb_lo = 0;
    const int jb_hi = qb2 + 1;

    for (int jb = jb_lo; jb <= jb_hi; jb++) {
        const int j0 = jb * 64;
        __syncthreads();   // previous iter done with K/V/P smem

        // K/V tiles: bf16 hi/lo cp.async copies
        for (int i = tid; i < 64 * 16; i += 256) {
            int r = i >> 4, ch = (i & 15) * 8;
            size_t src = (size_t)(b * SEQ + j0 + r) * NQKV + kvh * HDIM + ch;
            uint32_t dst = s_base + (uint32_t)((r * AQ_STR + ch) * 2);
            CP16(dst + S_KH * 2, qh_g + 4096 + src);
            CP16(dst + S_KL * 2, ql_g + 4096 + src);
            CP16(dst + S_VH * 2, qh_g + 5120 + src);
            CP16(dst + S_VL * 2, ql_g + 5120 + src);
        }
        CP_COMMIT();
        CP_WAIT0();
        __syncthreads();

        if (j0 > iw + 15 || j0 + 63 < iw - (WIN - 1)) continue;

        float s_acc[8][4];
#pragma unroll
        for (int nj = 0; nj < 8; nj++)
#pragma unroll
            for (int u = 0; u < 4; u++) s_acc[nj][u] = 0.f;

#pragma unroll
        for (int ks = 0; ks < 8; ks++) {
            uint32_t qh_f[4], ql_f[4];
            uint32_t aq = s_base + (uint32_t)((a_row * AQ_STR + ks * 16 + a_kof) * 2);
            LDSM4(qh_f, aq + S_QH * 2);
            LDSM4(ql_f, aq + S_QL * 2);
#pragma unroll
            for (int kp2 = 0; kp2 < 4; kp2 += 2) {
                uint32_t kh0[4], kl0[4], kh1[4], kl1[4];
                uint32_t ab0 = s_base + (uint32_t)((((kp2)     * 16 + kb_r) * AQ_STR + ks * 16 + kb_k) * 2);
                uint32_t ab1 = s_base + (uint32_t)((((kp2 + 1) * 16 + kb_r) * AQ_STR + ks * 16 + kb_k) * 2);
                LDSM4(kh0, ab0 + S_KH * 2);
                LDSM4(kl0, ab0 + S_KL * 2);
                LDSM4(kh1, ab1 + S_KH * 2);
                LDSM4(kl1, ab1 + S_KL * 2);
                const int a0 = kp2 * 2;
                MMA16816(s_acc[a0 + 0], qh_f, kh0[0], kh0[1]);
                MMA16816(s_acc[a0 + 1], qh_f, kh0[2], kh0[3]);
                MMA16816(s_acc[a0 + 2], qh_f, kh1[0], kh1[1]);
                MMA16816(s_acc[a0 + 3], qh_f, kh1[2], kh1[3]);
                MMA16816(s_acc[a0 + 0], qh_f, kl0[0], kl0[1]);
                MMA16816(s_acc[a0 + 1], qh_f, kl0[2], kl0[3]);
                MMA16816(s_acc[a0 + 2], qh_f, kl1[0], kl1[1]);
                MMA16816(s_acc[a0 + 3], qh_f, kl1[2], kl1[3]);
                MMA16816(s_acc[a0 + 0], ql_f, kh0[0], kh0[1]);
                MMA16816(s_acc[a0 + 1], ql_f, kh0[2], kh0[3]);
                MMA16816(s_acc[a0 + 2], ql_f, kh1[0], kh1[1]);
                MMA16816(s_acc[a0 + 3], ql_f, kh1[2], kh1[3]);
            }
        }

        const int i_lo = iw + rl;
        const int i_hi = i_lo + 8;
#pragma unroll
        for (int nj = 0; nj < 8; nj++) {
            int jg = j0 + nj * 8 + cq;
            if (jg     > i_lo || i_lo - jg     >= WIN) s_acc[nj][0] = -1e30f;
            if (jg + 1 > i_lo || i_lo - jg - 1 >= WIN) s_acc[nj][1] = -1e30f;
            if (jg     > i_hi || i_hi - jg     >= WIN) s_acc[nj][2] = -1e30f;
            if (jg + 1 > i_hi || i_hi - jg - 1 >= WIN) s_acc[nj][3] = -1e30f;
        }
        float mx_lo = -1e30f, mx_hi = -1e30f;
#pragma unroll
        for (int nj = 0; nj < 8; nj++) {
            mx_lo = fmaxf(mx_lo, fmaxf(s_acc[nj][0], s_acc[nj][1]));
            mx_hi = fmaxf(mx_hi, fmaxf(s_acc[nj][2], s_acc[nj][3]));
        }
        mx_lo = fmaxf(mx_lo, __shfl_xor_sync(0xffffffffu, mx_lo, 1));
        mx_lo = fmaxf(mx_lo, __shfl_xor_sync(0xffffffffu, mx_lo, 2));
        mx_hi = fmaxf(mx_hi, __shfl_xor_sync(0xffffffffu, mx_hi, 1));
        mx_hi = fmaxf(mx_hi, __shfl_xor_sync(0xffffffffu, mx_hi, 2));

        float mn_lo = fmaxf(m_lo, mx_lo);
        float mn_hi = fmaxf(m_hi, mx_hi);
        float f_lo = __expf(m_lo - mn_lo);
        float f_hi = __expf(m_hi - mn_hi);
        m_lo = mn_lo; m_hi = mn_hi;

        float sum_lo = 0.f, sum_hi = 0.f;
#pragma unroll
        for (int nj = 0; nj < 8; nj++) {
            float p0 = __expf(s_acc[nj][0] - mn_lo);
            float p1 = __expf(s_acc[nj][1] - mn_lo);
            float p2 = __expf(s_acc[nj][2] - mn_hi);
            float p3 = __expf(s_acc[nj][3] - mn_hi);
            sum_lo += p0 + p1;
            sum_hi += p2 + p3;
            __nv_bfloat16 h0, h1, h2, h3, l0, l1, l2, l3;
            split1(p0, h0, l0); split1(p1, h1, l1);
            split1(p2, h2, l2); split1(p3, h3, l3);
            int co = nj * 8 + cq;
            *(__nv_bfloat162*)(smb + S_PH + (wid * 16 + rl) * AP_STR + co)     = __nv_bfloat162(h0, h1);
            *(__nv_bfloat162*)(smb + S_PL + (wid * 16 + rl) * AP_STR + co)     = __nv_bfloat162(l0, l1);
            *(__nv_bfloat162*)(smb + S_PH + (wid * 16 + rl + 8) * AP_STR + co) = __nv_bfloat162(h2, h3);
            *(__nv_bfloat162*)(smb + S_PL + (wid * 16 + rl + 8) * AP_STR + co) = __nv_bfloat162(l2, l3);
        }
        sum_lo += __shfl_xor_sync(0xffffffffu, sum_lo, 1);
        sum_lo += __shfl_xor_sync(0xffffffffu, sum_lo, 2);
        sum_hi += __shfl_xor_sync(0xffffffffu, sum_hi, 1);
        sum_hi += __shfl_xor_sync(0xffffffffu, sum_hi, 2);
        l_lo = l_lo * f_lo + sum_lo;
        l_hi = l_hi * f_hi + sum_hi;

#pragma unroll
        for (int nj = 0; nj < 16; nj++) {
            o_acc[nj][0] *= f_lo; o_acc[nj][1] *= f_lo;
            o_acc[nj][2] *= f_hi; o_acc[nj][3] *= f_hi;
        }
        __syncwarp();

#pragma unroll
        for (int kc = 0; kc < 4; kc++) {
            uint32_t ph_f[4], pl_f[4];
            uint32_t ap = s_base + (uint32_t)((a_row * AP_STR + kc * 16 + a_kof) * 2);
            LDSM4(ph_f, ap + S_PH * 2);
            LDSM4(pl_f, ap + S_PL * 2);
#pragma unroll
            for (int nb2 = 0; nb2 < 8; nb2 += 2) {
                uint32_t vh0[4], vl0[4], vh1[4], vl1[4];
                uint32_t av0 = s_base + (uint32_t)(((kc * 16 + v_row) * AQ_STR + (nb2)     * 16 + v_col) * 2);
                uint32_t av1 = s_base + (uint32_t)(((kc * 16 + v_row) * AQ_STR + (nb2 + 1) * 16 + v_col) * 2);
                LDSM4T(vh0, av0 + S_VH * 2);
                LDSM4T(vl0, av0 + S_VL * 2);
                LDSM4T(vh1, av1 + S_VH * 2);
                LDSM4T(vl1, av1 + S_VL * 2);
                const int a0 = nb2 * 2;
                MMA16816(o_acc[a0 + 0], ph_f, vh0[0], vh0[1]);
                MMA16816(o_acc[a0 + 1], ph_f, vh0[2], vh0[3]);
                MMA16816(o_acc[a0 + 2], ph_f, vh1[0], vh1[1]);
                MMA16816(o_acc[a0 + 3], ph_f, vh1[2], vh1[3]);
                MMA16816(o_acc[a0 + 0], ph_f, vl0[0], vl0[1]);
                MMA16816(o_acc[a0 + 1], ph_f, vl0[2], vl0[3]);
                MMA16816(o_acc[a0 + 2], ph_f, vl1[0], vl1[1]);
                MMA16816(o_acc[a0 + 3], ph_f, vl1[2], vl1[3]);
                MMA16816(o_acc[a0 + 0], pl_f, vh0[0], vh0[1]);
                MMA16816(o_acc[a0 + 1], pl_f, vh0[2], vh0[3]);
                MMA16816(o_acc[a0 + 2], pl_f, vh1[0], vh1[1]);
                MMA16816(o_acc[a0 + 3], pl_f, vh1[2], vh1[3]);
            }
        }
    }

    // epilogue: O / l -> split hi/lo bf16 (feeds wo GEMM)
    float inv_lo = 1.0f / l_lo;
    float inv_hi = 1.0f / l_hi;
    const int i_lo = iw + rl;
#pragma unroll
    for (int nj = 0; nj < 16; nj++) {
        int col = nj * 8 + cq;
        size_t o0 = ((size_t)(b * SEQ + i_lo)     * HQ + h) * HDIM + col;
        size_t o1 = ((size_t)(b * SEQ + i_lo + 8) * HQ + h) * HDIM + col;
        float v0 = o_acc[nj][0] * inv_lo, v1 = o_acc[nj][1] * inv_lo;
        float v2 = o_acc[nj][2] * inv_hi, v3 = o_acc[nj][3] * inv_hi;
        __nv_bfloat16 h0, h1, h2, h3, l0, l1, l2, l3;
        split1(v0, h0, l0); split1(v1, h1, l1);
        split1(v2, h2, l2); split1(v3, h3, l3);
        *(__nv_bfloat162*)(oh + o0) = __nv_bfloat162(h0, h1);
        *(__nv_bfloat162*)(ol + o0) = __nv_bfloat162(l0, l1);
        *(__nv_bfloat162*)(oh + o1) = __nv_bfloat162(h2, h3);
        *(__nv_bfloat162*)(ol + o1) = __nv_bfloat162(l2, l3);
    }
}

// ================= launch =================
extern "C" void kernel_launch(void* const* d_in, const int* in_sizes, int n_in,
                              void* d_out, int out_size)
{
    (void)in_sizes; (void)n_in; (void)out_size;
    const float* x  = (const float*)d_in[0];
    const float* cs = (const float*)d_in[1];
    const float* sn = (const float*)d_in[2];
    const float* wq = (const float*)d_in[3];
    const float* wk = (const float*)d_in[4];
    const float* wv = (const float*)d_in[5];
    const float* wo = (const float*)d_in[6];
    float* out = (float*)d_out;

    __nv_bfloat16 *qhp, *qlp, *ahp, *alp, *whp, *wlp;
    cudaGetSymbolAddress((void**)&qhp, g_qkv_hi);
    cudaGetSymbolAddress((void**)&qlp, g_qkv_lo);
    cudaGetSymbolAddress((void**)&ahp, g_a_hi);
    cudaGetSymbolAddress((void**)&alp, g_a_lo);
    cudaGetSymbolAddress((void**)&whp, g_w_hi);
    cudaGetSymbolAddress((void**)&wlp, g_w_lo);

    cudaFuncSetAttribute(gemm_mma<0>, cudaFuncAttributeMaxDynamicSharedMemorySize, GEMM_SMEM);
    cudaFuncSetAttribute(gemm_mma<1>, cudaFuncAttributeMaxDynamicSharedMemorySize, GEMM_SMEM);
    cudaFuncSetAttribute(attn_mma,    cudaFuncAttributeMaxDynamicSharedMemorySize, ATTN_SMEM);

    const int NELEM = T_TOK * DIMV;
    dim3 cvtb(32, 8);

    // x -> hi/lo
    cvt_split<<<(NELEM / 4) / 256, 256>>>(x, ahp, alp);

    // fused qkv weights -> Wt[6144, 4096]
    cvt_wt_qkv<<<dim3(NQKV / 32, DIMV / 32), cvtb>>>(wq, wk, wv, whp, wlp);

    // qkv = x @ [wq|wk|wv], epilogue: scale(q) + rope(q,k) + split -> bf16 hi/lo
    gemm_mma<1><<<dim3(NQKV / 128, T_TOK / 64), 128, GEMM_SMEM>>>(
        ahp, alp, whp, wlp, nullptr, qhp, qlp, cs, sn, DIMV, NQKV);

    // attention (HMMA) reads pre-split qkv, writes split ao -> a buffers
    attn_mma<<<dim3(SEQ / 128, HQ, BATCH), 256, ATTN_SMEM>>>(qhp, qlp, ahp, alp);

    // out = ao @ wo
    cvt_wt<<<dim3(DIMV / 32, (HQ * HDIM) / 32), cvtb>>>(wo, whp, wlp, HQ * HDIM, DIMV);
    gemm_mma<0><<<dim3(DIMV / 128, T_TOK / 64), 128, GEMM_SMEM>>>(
        ahp, alp, whp, wlp, out, nullptr, nullptr, nullptr, nullptr, DIMV, HQ * HDIM);
}